// round 13
// baseline (speedup 1.0000x reference)
#include <cuda_runtime.h>
#include <math.h>

#define Sc 2048
#define Dc 2048
#define NTS 512
#define FULLM 0xffffffffu
#define IS2 0.70710678118654752440f
#define HAL 72
#define LD 2192

// ---------------- device scratch ----------------------------------------
__device__ float g_ssq[8 * Sc];   // sum over d of dwt coeff^2
__device__ float g_pt[8 * Sc];    // per-token dot with w_val
__device__ float g_rhof[8 * Sc];  // final rho_f (normalized)
__device__ int g_flags[16];       // [0..7] prep tile counts, [8..15] rhof done
__device__ int g_ctr[2];          // work counters: prep tiles, out tiles

// ---------------- compile-time leray taps --------------------------------
struct Taps {
    float k[68];    // leray taps, disp -32..+32 (65 used, pad 68)
    float k2[68];   // 0.0125 * (kl conv kl), disp -32..+32 (65 used, pad 68)
};
__host__ __device__ constexpr Taps make_taps() {
    Taps t = {};
    double p[256] = {};
    double pn[256] = {};
    for (int it = 0; it < 50; it++) {
        for (int i = 0; i < 256; i++) {
            double l = (i > 0) ? p[i - 1] : 0.0;
            double r = (i < 255) ? p[i + 1] : 0.0;
            double bb = (i == 128) ? 1.0 : ((i == 129) ? -1.0 : 0.0);
            pn[i] = 0.5 * (r + l - bb);
        }
        for (int i = 0; i < 256; i++) p[i] = pn[i];
    }
    double kl[103] = {};
    for (int j = 0; j < 103; j++) {
        int i = 77 + j;                      // disp = j - 51
        double del = (i == 128) ? 1.0 : 0.0;
        kl[j] = del - (p[i + 1] - p[i]);
    }
    for (int j = 0; j < 68; j++)
        t.k[j] = (j < 65) ? (float)kl[j + 19] : 0.0f;
    for (int j = 0; j < 68; j++) {
        double s = 0.0;
        if (j < 65) {
            int d = j - 32;
            for (int a = -51; a <= 51; a++) {
                int e = d - a;
                if (e >= -51 && e <= 51) s += kl[a + 51] * kl[e + 51];
            }
            s *= 0.0125;                     // INNER_LR / B folded in
        }
        t.k2[j] = (float)s;
    }
    return t;
}

// ---------------- small helpers ------------------------------------------
__device__ __forceinline__ float4 ld4(const float* p) { return *(const float4*)p; }
__device__ __forceinline__ void st4(float* p, float4 v) { *(float4*)p = v; }
__device__ __forceinline__ void st4h(float* A, int i0, float4 v) {
    *(float4*)(A + i0) = v;
    if (i0 < HAL) *(float4*)(A + i0 + Sc) = v;
    if (i0 >= Sc - HAL) *(float4*)(A + i0 - Sc) = v;
}
__device__ __forceinline__ void sth(float* A, int i, float v) {
    A[i] = v;
    if (i < HAL) A[i + Sc] = v;
    if (i >= Sc - HAL) A[i - Sc] = v;
}

// ------------- single-barrier reductions (512 thr, 16 warps) -------------
__device__ __forceinline__ float bsum1(float v, float* red, int& sl) {
#pragma unroll
    for (int o = 16; o; o >>= 1) v += __shfl_xor_sync(FULLM, v, o);
    int lane = threadIdx.x & 31, wid = threadIdx.x >> 5;
    if (lane == 0) red[sl * 16 + wid] = v;
    __syncthreads();
    float s = 0.0f;
    const float* rr = red + sl * 16;
#pragma unroll
    for (int w = 0; w < 16; w++) s += rr[w];
    sl ^= 1;
    return s;
}

__device__ __forceinline__ float bsum2(float v, float v2, float* red, float* red2,
                                       int& sl, float* out2) {
#pragma unroll
    for (int o = 16; o; o >>= 1) {
        v += __shfl_xor_sync(FULLM, v, o);
        v2 += __shfl_xor_sync(FULLM, v2, o);
    }
    int lane = threadIdx.x & 31, wid = threadIdx.x >> 5;
    if (lane == 0) { red[sl * 16 + wid] = v; red2[wid] = v2; }
    __syncthreads();
    float s = 0.0f, s2 = 0.0f;
    const float* rr = red + sl * 16;
#pragma unroll
    for (int w = 0; w < 16; w++) { s += rr[w]; s2 += red2[w]; }
    sl ^= 1;
    *out2 = s2;
    return s;
}

__device__ __forceinline__ void partial_store(float p, float* red, int sl) {
#pragma unroll
    for (int o = 16; o; o >>= 1) p += __shfl_xor_sync(FULLM, p, o);
    int lane = threadIdx.x & 31, wid = threadIdx.x >> 5;
    if (lane == 0) red[sl * 16 + wid] = p;
}
__device__ __forceinline__ float partial_read(const float* red, int& sl) {
    float s = 0.0f;
    const float* rr = red + sl * 16;
#pragma unroll
    for (int w = 0; w < 16; w++) s += rr[w];
    sl ^= 1;
    return s;
}

__device__ __forceinline__ float bmax1(float v, float* mred) {
#pragma unroll
    for (int o = 16; o; o >>= 1) v = fmaxf(v, __shfl_xor_sync(FULLM, v, o));
    int lane = threadIdx.x & 31, wid = threadIdx.x >> 5;
    if (lane == 0) mred[wid] = v;
    __syncthreads();
    float m = mred[0];
#pragma unroll
    for (int w = 1; w < 16; w++) m = fmaxf(m, mred[w]);
    return m;
}

__device__ __forceinline__ float bmaxcnt1(float m, float c, float* mred, float* cnt_out) {
#pragma unroll
    for (int o = 16; o; o >>= 1) {
        float m2 = __shfl_xor_sync(FULLM, m, o);
        float c2 = __shfl_xor_sync(FULLM, c, o);
        if (m2 > m) { m = m2; c = c2; }
        else if (m2 == m) { c += c2; }
    }
    int lane = threadIdx.x & 31, wid = threadIdx.x >> 5;
    if (lane == 0) { mred[wid] = m; mred[16 + wid] = c; }
    __syncthreads();
    float M = mred[0];
#pragma unroll
    for (int w = 1; w < 16; w++) M = fmaxf(M, mred[w]);
    float C = 0.0f;
#pragma unroll
    for (int w = 0; w < 16; w++) C += (mred[w] == M) ? mred[16 + w] : 0.0f;
    *cnt_out = C;
    return M;
}

// ---------------- leray: 65-tap conv, immediate taps (init only) ---------
__device__ __forceinline__ void conv_leray(float* __restrict__ dst,
                                           const float* __restrict__ src) {
    constexpr Taps TAPS = make_taps();
    int i0 = 4 * threadIdx.x;
    const float* S = src + i0 - 32;
    float4 cur = ld4(S);
    float a0 = 0.0f, a1 = 0.0f, a2 = 0.0f, a3 = 0.0f;
#pragma unroll
    for (int m = 0; m < 17; m++) {
        float4 nxt = ld4(S + 4 * m + 4);
        const float kx = TAPS.k[4 * m], ky = TAPS.k[4 * m + 1];
        const float kz = TAPS.k[4 * m + 2], kw = TAPS.k[4 * m + 3];
        a0 += kx * cur.x + ky * cur.y + kz * cur.z + kw * cur.w;
        a1 += kx * cur.y + ky * cur.z + kz * cur.w + kw * nxt.x;
        a2 += kx * cur.z + ky * cur.w + kz * nxt.x + kw * nxt.y;
        a3 += kx * cur.w + ky * nxt.x + kz * nxt.y + kw * nxt.z;
        cur = nxt;
    }
    st4h(dst, i0, make_float4(a0, a1, a2, a3));
    __syncthreads();
}

// ------- fused: up -= (lr/B)*leray^2(ub), 65-tap imm conv, no barrier ----
__device__ __forceinline__ void conv2_update(float* __restrict__ up,
                                             const float* __restrict__ ub) {
    constexpr Taps TAPS = make_taps();
    int i0 = 4 * threadIdx.x;
    const float* S = ub + i0 - 32;
    float4 cur = ld4(S);
    float a0 = 0.0f, a1 = 0.0f, a2 = 0.0f, a3 = 0.0f;
#pragma unroll
    for (int m = 0; m < 17; m++) {
        float4 nxt = ld4(S + 4 * m + 4);
        const float kx = TAPS.k2[4 * m], ky = TAPS.k2[4 * m + 1];
        const float kz = TAPS.k2[4 * m + 2], kw = TAPS.k2[4 * m + 3];
        a0 += kx * cur.x + ky * cur.y + kz * cur.z + kw * cur.w;
        a1 += kx * cur.y + ky * cur.z + kz * cur.w + kw * nxt.x;
        a2 += kx * cur.z + ky * cur.w + kz * nxt.x + kw * nxt.y;
        a3 += kx * cur.w + ky * nxt.x + kz * nxt.y + kw * nxt.z;
        cur = nxt;
    }
    float4 u = ld4(up + i0);
    st4h(up, i0, make_float4(u.x - a0, u.y - a1, u.z - a2, u.w - a3));
}

// ---- forward advect: store RAW y, one barrier, return Z -----------------
__device__ __forceinline__ float advect_fwd(float* __restrict__ dst,
                                            const float* __restrict__ r, float iZr,
                                            const float uv[5],
                                            float dt, float* red, int& sl) {
    int i0 = 4 * threadIdx.x;
    float4 r0 = ld4(r + i0);
    float rv[6] = {r[i0 - 1] * iZr, r0.x * iZr, r0.y * iZr, r0.z * iZr, r0.w * iZr,
                   r[i0 + 4] * iZr};
    float F[5];
#pragma unroll
    for (int k = 0; k < 5; k++)
        F[k] = uv[k] > 0.0f ? uv[k] * rv[k] : uv[k] * rv[k + 1];
    float y[4], part = 0.0f;
#pragma unroll
    for (int e = 0; e < 4; e++) {
        y[e] = fabsf(rv[e + 1] - dt * (F[e + 1] - F[e])) + 1e-8f;
        part += y[e];
    }
    st4h(dst, i0, make_float4(y[0], y[1], y[2], y[3]));
    return bsum1(part, red, sl);
}

// ---- forward advect for r4: also reduces dot((1-v), y_raw) --------------
__device__ __forceinline__ float advect_fwd_dot(float* __restrict__ dst,
                                                const float* __restrict__ r, float iZr,
                                                const float uv[5],
                                                const float* __restrict__ vA,
                                                float dt, float* red, float* red2,
                                                int& sl, float* dotraw_out) {
    int i0 = 4 * threadIdx.x;
    float4 r0 = ld4(r + i0);
    float rv[6] = {r[i0 - 1] * iZr, r0.x * iZr, r0.y * iZr, r0.z * iZr, r0.w * iZr,
                   r[i0 + 4] * iZr};
    float F[5];
#pragma unroll
    for (int k = 0; k < 5; k++)
        F[k] = uv[k] > 0.0f ? uv[k] * rv[k] : uv[k] * rv[k + 1];
    float4 v4 = ld4(vA + i0);
    float vb[4] = {1.0f - v4.x, 1.0f - v4.y, 1.0f - v4.z, 1.0f - v4.w};
    float y[4], part = 0.0f, part2 = 0.0f;
#pragma unroll
    for (int e = 0; e < 4; e++) {
        y[e] = fabsf(rv[e + 1] - dt * (F[e + 1] - F[e])) + 1e-8f;
        part += y[e];
        part2 += vb[e] * y[e];
    }
    st4h(dst, i0, make_float4(y[0], y[1], y[2], y[3]));
    return bsum2(part, part2, red, red2, sl, dotraw_out);
}

// ---- final outer advect (with kappa), stores NORMALIZED -----------------
__device__ __forceinline__ void advect_final(float* __restrict__ dst,
                                             const float* __restrict__ r,
                                             const float* __restrict__ u,
                                             float dt, float kap, float* red, int& sl) {
    int i0 = 4 * threadIdx.x;
    float4 r0 = ld4(r + i0);
    float rv[6] = {r[i0 - 1], r0.x, r0.y, r0.z, r0.w, r[i0 + 4]};
    float4 u0 = ld4(u + i0);
    float uv[5] = {u[i0 - 1], u0.x, u0.y, u0.z, u0.w};
    float F[5];
#pragma unroll
    for (int k = 0; k < 5; k++)
        F[k] = uv[k] > 0.0f ? uv[k] * rv[k] : uv[k] * rv[k + 1];
    float y[4], part = 0.0f;
#pragma unroll
    for (int e = 0; e < 4; e++) {
        float a = rv[e + 1] - dt * (F[e + 1] - F[e])
                + kap * dt * (rv[e + 2] + rv[e] - 2.0f * rv[e + 1]);
        y[e] = fabsf(a) + 1e-8f;
        part += y[e];
    }
    float Z = bsum1(part, red, sl);
    float iZ = 1.0f / Z;
    st4h(dst, i0, make_float4(y[0] * iZ, y[1] * iZ, y[2] * iZ, y[3] * iZ));
}

// ---- FIRST backward step (t=4): rb=(1-v), dot from fwd; SETS ub ---------
__device__ __forceinline__ float bwd_first(const float* __restrict__ rt, float iZt,
                                           float Zn, float dotraw,
                                           const float uv[5], float dt,
                                           const float* __restrict__ vA,
                                           float* __restrict__ abA,
                                           float rb[4], float ub[4],
                                           float* red, int sl) {
    int i0 = 4 * threadIdx.x;
    float iZn = 1.0f / Zn;
    float dot = dotraw * iZn;

    float4 r0 = ld4(rt + i0);
    float rr[4] = {r0.x, r0.y, r0.z, r0.w};
    float rv[6] = {rt[i0 - 1] * iZt, r0.x * iZt, r0.y * iZt, r0.z * iZt, r0.w * iZt,
                   rt[i0 + 4] * iZt};
    float F[5];
#pragma unroll
    for (int k = 0; k < 5; k++)
        F[k] = uv[k] > 0.0f ? uv[k] * rv[k] : uv[k] * rv[k + 1];

    float4 v4 = ld4(vA + i0);
    float rbl[4] = {1.0f - v4.x, 1.0f - v4.y, 1.0f - v4.z, 1.0f - v4.w};
    float ab[4], dtl = 0.0f;
#pragma unroll
    for (int e = 0; e < 4; e++) {
        float a = rv[e + 1] - dt * (F[e + 1] - F[e]);
        float s = (a > 0.0f) ? 1.0f : ((a < 0.0f) ? -1.0f : 0.0f);
        ab[e] = (rbl[e] - dot) * iZn * s;
        dtl -= ab[e] * (F[e + 1] - F[e]);
    }
    st4h(abA, i0, make_float4(ab[0], ab[1], ab[2], ab[3]));
    __syncthreads();

    float abv[6] = {abA[i0 - 1], ab[0], ab[1], ab[2], ab[3], abA[i0 + 4]};
    float Fb[5];
#pragma unroll
    for (int k = 0; k < 5; k++)
        Fb[k] = -dt * (abv[k] - abv[k + 1]);
#pragma unroll
    for (int e = 0; e < 4; e++) {
        ub[e] = Fb[e + 1] * (uv[e + 1] > 0.0f ? rv[e + 1] : rv[e + 2]);
        rb[e] = ab[e] + (uv[e + 1] > 0.0f ? Fb[e + 1] * uv[e + 1] : 0.0f)
                      + (uv[e] > 0.0f ? 0.0f : Fb[e] * uv[e]);
    }
    partial_store(rb[0] * rr[0] + rb[1] * rr[1] + rb[2] * rr[2] + rb[3] * rr[3],
                  red, sl);
    return dtl;
}

// ---- middle backward step: entry barrier publishes the pending partial --
__device__ __forceinline__ float bwd_mid(const float* __restrict__ rt, float iZt,
                                         float Zn,
                                         const float uv[5], float dt,
                                         float* __restrict__ abA,
                                         float rb[4], float ub[4],
                                         float* red, int& sl) {
    int i0 = 4 * threadIdx.x;
    __syncthreads();
    float dotraw = partial_read(red, sl);
    float iZn = 1.0f / Zn;
    float dot = dotraw * iZn;

    float4 r0 = ld4(rt + i0);
    float rr[4] = {r0.x, r0.y, r0.z, r0.w};
    float rv[6] = {rt[i0 - 1] * iZt, r0.x * iZt, r0.y * iZt, r0.z * iZt, r0.w * iZt,
                   rt[i0 + 4] * iZt};
    float F[5];
#pragma unroll
    for (int k = 0; k < 5; k++)
        F[k] = uv[k] > 0.0f ? uv[k] * rv[k] : uv[k] * rv[k + 1];

    float ab[4], dtl = 0.0f;
#pragma unroll
    for (int e = 0; e < 4; e++) {
        float a = rv[e + 1] - dt * (F[e + 1] - F[e]);
        float s = (a > 0.0f) ? 1.0f : ((a < 0.0f) ? -1.0f : 0.0f);
        ab[e] = (rb[e] - dot) * iZn * s;
        dtl -= ab[e] * (F[e + 1] - F[e]);
    }
    st4h(abA, i0, make_float4(ab[0], ab[1], ab[2], ab[3]));
    __syncthreads();

    float abv[6] = {abA[i0 - 1], ab[0], ab[1], ab[2], ab[3], abA[i0 + 4]};
    float Fb[5];
#pragma unroll
    for (int k = 0; k < 5; k++)
        Fb[k] = -dt * (abv[k] - abv[k + 1]);
#pragma unroll
    for (int e = 0; e < 4; e++) {
        ub[e] += Fb[e + 1] * (uv[e + 1] > 0.0f ? rv[e + 1] : rv[e + 2]);
        rb[e] = ab[e] + (uv[e + 1] > 0.0f ? Fb[e + 1] * uv[e + 1] : 0.0f)
                      + (uv[e] > 0.0f ? 0.0f : Fb[e] * uv[e]);
    }
    partial_store(rb[0] * rr[0] + rb[1] * rr[1] + rb[2] * rr[2] + rb[3] * rr[3],
                  red, sl);
    return dtl;
}

// ---- LAST backward step: dtbar fused into the abA-publish barrier -------
__device__ __forceinline__ float bwd_last(const float* __restrict__ rt,
                                          float Zn,
                                          const float uv[5], float dt, float dtl_in,
                                          float* __restrict__ abA,
                                          float rb[4], float ub[4],
                                          float* red, float* red2, int& sl) {
    int i0 = 4 * threadIdx.x;
    __syncthreads();
    float dotraw = partial_read(red, sl);
    float iZn = 1.0f / Zn;
    float dot = dotraw * iZn;

    float4 r0 = ld4(rt + i0);
    float rv[6] = {rt[i0 - 1], r0.x, r0.y, r0.z, r0.w, rt[i0 + 4]};  // iZt = 1
    float F[5];
#pragma unroll
    for (int k = 0; k < 5; k++)
        F[k] = uv[k] > 0.0f ? uv[k] * rv[k] : uv[k] * rv[k + 1];

    float ab[4], dtl = dtl_in;
#pragma unroll
    for (int e = 0; e < 4; e++) {
        float a = rv[e + 1] - dt * (F[e + 1] - F[e]);
        float s = (a > 0.0f) ? 1.0f : ((a < 0.0f) ? -1.0f : 0.0f);
        ab[e] = (rb[e] - dot) * iZn * s;
        dtl -= ab[e] * (F[e + 1] - F[e]);
    }
    st4h(abA, i0, make_float4(ab[0], ab[1], ab[2], ab[3]));
    float t = dtl;
#pragma unroll
    for (int o = 16; o; o >>= 1) t += __shfl_xor_sync(FULLM, t, o);
    int lane = threadIdx.x & 31, wid = threadIdx.x >> 5;
    if (lane == 0) red2[wid] = t;
    __syncthreads();
    float dtbar = 0.0f;
#pragma unroll
    for (int w = 0; w < 16; w++) dtbar += red2[w];

    float abv[6] = {abA[i0 - 1], ab[0], ab[1], ab[2], ab[3], abA[i0 + 4]};
    float Fb[5];
#pragma unroll
    for (int k = 0; k < 5; k++)
        Fb[k] = -dt * (abv[k] - abv[k + 1]);
#pragma unroll
    for (int e = 0; e < 4; e++)
        ub[e] += Fb[e + 1] * (uv[e + 1] > 0.0f ? rv[e + 1] : rv[e + 2]);
    return dtbar;
}

// ---------------- sim body: one CTA, batch b -----------------------------
#define SIM_SMEM ((2128 + 11 * LD) * 4)

__device__ void sim_body(int b, const float* __restrict__ phi_g, float* sm) {
    float* red  = sm;          // 32 (2 slots x 16)
    float* red2 = sm + 32;     // 16
    float* mred = sm + 48;     // 32
    float* phiA = sm + 80;     // 2048
    float* arr  = sm + 2128;   // 11 x LD haloed arrays
    float* vA   = arr + 0 * LD + HAL;
    float* up0A = arr + 1 * LD + HAL;
    float* upA  = arr + 2 * LD + HAL;
    float* rhoA = arr + 3 * LD + HAL;
    float* spA  = arr + 4 * LD + HAL;
    float* r1A  = arr + 5 * LD + HAL;
    float* r2A  = arr + 6 * LD + HAL;
    float* r3A  = arr + 7 * LD + HAL;
    float* r4A  = arr + 8 * LD + HAL;
    float* abA  = arr + 9 * LD + HAL;
    float* ubA  = arr + 10 * LD + HAL;

    int tid = threadIdx.x;
    int i0 = 4 * tid;
    int sl = 0;

    st4(phiA + i0, ld4(phi_g + i0));

    {
        float4 s4 = ld4(g_ssq + b * Sc + i0);
        float y0 = sqrtf(s4.x) + 1e-8f, y1 = sqrtf(s4.y) + 1e-8f;
        float y2 = sqrtf(s4.z) + 1e-8f, y3 = sqrtf(s4.w) + 1e-8f;
        float Z = bsum1(y0 + y1 + y2 + y3, red, sl);
        float iZ = 1.0f / Z;
        st4h(rhoA, i0, make_float4(y0 * iZ, y1 * iZ, y2 * iZ, y3 * iZ));
    }

    st4(r1A + i0, ld4(g_pt + b * Sc + i0));
    __syncthreads();
#pragma unroll
    for (int s = 0; s < 2; s++) {           // level 1
        int j = 2 * tid + s;
        float e = r1A[2 * j], o = r1A[2 * j + 1];
        sth(vA, 1024 + j, (e - o) * IS2);
        r2A[j] = (e + o) * IS2;
    }
    __syncthreads();
    {                                       // level 2
        float e = r2A[2 * tid], o = r2A[2 * tid + 1];
        sth(vA, 512 + tid, (e - o) * IS2);
        r1A[tid] = (e + o) * IS2;
    }
    __syncthreads();
    if (tid < 256) {                        // level 3
        float e = r1A[2 * tid], o = r1A[2 * tid + 1];
        sth(vA, 256 + tid, (e - o) * IS2);
        sth(vA, tid, (e + o) * IS2);
    }
    __syncthreads();
    {
        float4 v4 = ld4(vA + i0);
        float y0 = 45.254833995939045f * fabsf(v4.x) + 1e-8f;
        float y1 = 45.254833995939045f * fabsf(v4.y) + 1e-8f;
        float y2 = 45.254833995939045f * fabsf(v4.z) + 1e-8f;
        float y3 = 45.254833995939045f * fabsf(v4.w) + 1e-8f;
        float Z = bsum1(y0 + y1 + y2 + y3, red, sl);
        float iZ = 1.0f / Z;
        st4h(vA, i0, make_float4(y0 * iZ, y1 * iZ, y2 * iZ, y3 * iZ));
        __syncthreads();
    }

    {
        float4 v0 = ld4(vA + i0);
        float v4n = vA[i0 + 4];
        st4h(ubA, i0, make_float4(v0.y - v0.x, v0.z - v0.y, v0.w - v0.z, v4n - v0.w));
        __syncthreads();
        conv_leray(up0A, ubA);
    }

    float* rho = rhoA;
    float* spare = spA;

#pragma unroll 1
    for (int k = 0; k < 3; k++) {
        float kap = (k == 0) ? 0.01f : ((k == 1) ? 0.005f : 0.0f);

        for (int q = 4 * tid; q < LD; q += 4 * NTS)
            st4(arr + 2 * LD + q, ld4(arr + 1 * LD + q));

        {
            float4 rh = ld4(rho + i0);
            float4 ph = ld4(phiA + i0);
            float w0 = fabsf(rh.x * expf(-0.1f * (ph.x + logf(rh.x)))) + 1e-8f;
            float w1 = fabsf(rh.y * expf(-0.1f * (ph.y + logf(rh.y)))) + 1e-8f;
            float w2 = fabsf(rh.z * expf(-0.1f * (ph.z + logf(rh.z)))) + 1e-8f;
            float w3 = fabsf(rh.w * expf(-0.1f * (ph.w + logf(rh.w)))) + 1e-8f;
            float Z = bsum1(w0 + w1 + w2 + w3, red, sl);
            float iZ = 1.0f / Z;
            st4h(rho, i0, make_float4(w0 * iZ, w1 * iZ, w2 * iZ, w3 * iZ));
        }

#pragma unroll 1
        for (int is = 0; is < 5; is++) {
            float4 up4 = ld4(upA + i0);
            float a0 = fabsf(up4.x), a1 = fabsf(up4.y);
            float a2 = fabsf(up4.z), a3 = fabsf(up4.w);
            float lm = fmaxf(fmaxf(a0, a1), fmaxf(a2, a3));
            float lc = (a0 == lm ? 1.0f : 0.0f) + (a1 == lm ? 1.0f : 0.0f)
                     + (a2 == lm ? 1.0f : 0.0f) + (a3 == lm ? 1.0f : 0.0f);
            float nt;
            float m = bmaxcnt1(lm, lc, mred, &nt);
            float dt = 0.4f / (m + 1e-8f);

            float uv[5] = {upA[i0 - 1], up4.x, up4.y, up4.z, up4.w};

            float z0 = advect_fwd(r1A, rho, 1.0f, uv, dt, red, sl);
            float z1 = advect_fwd(r2A, r1A, 1.0f / z0, uv, dt, red, sl);
            float z2 = advect_fwd(r3A, r2A, 1.0f / z1, uv, dt, red, sl);
            float dotraw;
            float z3 = advect_fwd_dot(r4A, r3A, 1.0f / z2, uv, vA, dt,
                                      red, red2, sl, &dotraw);

            float rb[4], ub[4];
            float dtl = bwd_first(r3A, 1.0f / z2, z3, dotraw, uv, dt,
                                  vA, abA, rb, ub, red, sl);
            dtl += bwd_mid(r2A, 1.0f / z1, z2, uv, dt, abA, rb, ub, red, sl);
            dtl += bwd_mid(r1A, 1.0f / z0, z1, uv, dt, abA, rb, ub, red, sl);
            float dtbar = bwd_last(rho, z0, uv, dt, dtl, abA, rb, ub,
                                   red, red2, sl);

            float mbar = dtbar * (-dt * dt * 2.5f);
            {
                float inv_nt = mbar / nt;
                ub[0] += (a0 == m) ? inv_nt * ((up4.x > 0.0f) ? 1.0f : -1.0f) : 0.0f;
                ub[1] += (a1 == m) ? inv_nt * ((up4.y > 0.0f) ? 1.0f : -1.0f) : 0.0f;
                ub[2] += (a2 == m) ? inv_nt * ((up4.z > 0.0f) ? 1.0f : -1.0f) : 0.0f;
                ub[3] += (a3 == m) ? inv_nt * ((up4.w > 0.0f) ? 1.0f : -1.0f) : 0.0f;
                st4h(ubA, i0, make_float4(ub[0], ub[1], ub[2], ub[3]));
            }
            __syncthreads();

            conv2_update(upA, ubA);
        }

        {
            float4 up4 = ld4(upA + i0);
            float lm = fmaxf(fmaxf(fabsf(up4.x), fabsf(up4.y)),
                             fmaxf(fabsf(up4.z), fabsf(up4.w)));
            float mm = bmax1(lm, mred);
            float dt = 0.4f / (mm + 1e-8f);
            advect_final(spare, rho, upA, dt, kap, red, sl);
            float* tmp = rho; rho = spare; spare = tmp;
        }
    }

    {
        float4 rh = ld4(rho + i0);
        float4 v4 = ld4(vA + i0);
        float f0 = rh.x + 0.1f * v4.x, f1 = rh.y + 0.1f * v4.y;
        float f2 = rh.z + 0.1f * v4.z, f3 = rh.w + 0.1f * v4.w;
        float Z = bsum1(f0 + f1 + f2 + f3, red, sl);
        float iZ = 1.0f / Z;
        st4(g_rhof + b * Sc + i0, make_float4(f0 * iZ, f1 * iZ, f2 * iZ, f3 * iZ));
    }
}

// ---------------- prep tile (512 threads, 1 float4 chunk each) -----------
__device__ void prep_tile(int t, const float* __restrict__ x,
                          const float* __restrict__ wval, float* sred) {
    int b = t >> 8, g = t & 255;
    int tid = threadIdx.x;
    const float4* xv = (const float4*)(x + ((size_t)b * Sc + 8 * (size_t)g) * Dc);
    float4 w4 = ((const float4*)wval)[tid];

    float acc[16];
#pragma unroll
    for (int i = 0; i < 16; i++) acc[i] = 0.0f;

    float xr[4][8];
#pragma unroll
    for (int r = 0; r < 8; r++) {
        float4 q = xv[r * 512 + tid];
        xr[0][r] = q.x; xr[1][r] = q.y; xr[2][r] = q.z; xr[3][r] = q.w;
    }
    float wc[4] = {w4.x, w4.y, w4.z, w4.w};
#pragma unroll
    for (int cc = 0; cc < 4; cc++) {
        const float* X = xr[cc];
        float w = wc[cc];
#pragma unroll
        for (int r = 0; r < 8; r++) acc[8 + r] += X[r] * w;
        float a10 = (X[0] + X[1]) * IS2, d10 = (X[0] - X[1]) * IS2;
        float a11 = (X[2] + X[3]) * IS2, d11 = (X[2] - X[3]) * IS2;
        float a12 = (X[4] + X[5]) * IS2, d12 = (X[4] - X[5]) * IS2;
        float a13 = (X[6] + X[7]) * IS2, d13 = (X[6] - X[7]) * IS2;
        float a20 = (a10 + a11) * IS2, d20 = (a10 - a11) * IS2;
        float a21 = (a12 + a13) * IS2, d21 = (a12 - a13) * IS2;
        float a3 = (a20 + a21) * IS2, d3 = (a20 - a21) * IS2;
        acc[0] += a3 * a3;   acc[1] += d3 * d3;
        acc[2] += d20 * d20; acc[3] += d21 * d21;
        acc[4] += d10 * d10; acc[5] += d11 * d11;
        acc[6] += d12 * d12; acc[7] += d13 * d13;
    }
#pragma unroll
    for (int off = 16; off; off >>= 1)
#pragma unroll
        for (int j = 0; j < 16; j++) acc[j] += __shfl_xor_sync(FULLM, acc[j], off);

    int lane = tid & 31, wid = tid >> 5;
    if (lane == 0)
#pragma unroll
        for (int j = 0; j < 16; j++) sred[wid * 16 + j] = acc[j];
    __syncthreads();
    if (tid < 16) {
        float s = 0.0f;
#pragma unroll
        for (int w = 0; w < 16; w++) s += sred[w * 16 + tid];
        int base = b * Sc;
        if (tid < 8) {
            int idx;
            if (tid == 0) idx = g;
            else if (tid == 1) idx = 256 + g;
            else if (tid < 4) idx = 512 + 2 * g + (tid - 2);
            else idx = 1024 + 4 * g + (tid - 4);
            g_ssq[base + idx] = s;
        } else {
            g_pt[base + 8 * g + (tid - 8)] = s;
        }
    }
    __threadfence();
    __syncthreads();          // stores visible; also protects sred reuse
    if (tid == 0) atomicAdd(&g_flags[b], 1);
}

// ---------------- out tile (512 threads, 1 float4 chunk each) ------------
__device__ void out_tile(int t, const float* __restrict__ bw,
                         float* __restrict__ out) {
    int b = t >> 8, g = t & 255;
    int tid = threadIdx.x;
    const float* rf = g_rhof + b * Sc;
    float rfA = rf[g];
    float rf3 = rf[256 + g];
    float rf2a = rf[512 + 2 * g], rf2b = rf[512 + 2 * g + 1];
    float rf1_0 = rf[1024 + 4 * g], rf1_1 = rf[1024 + 4 * g + 1];
    float rf1_2 = rf[1024 + 4 * g + 2], rf1_3 = rf[1024 + 4 * g + 3];

    const float C8 = 0.35355339059327376220f;
    float cA = rfA * C8;
    float c3 = rf3 * C8;
    float c2arr[2] = {rf2a * 0.5f, rf2b * 0.5f};
    float c1arr[4] = {rf1_0 * IS2, rf1_1 * IS2, rf1_2 * IS2, rf1_3 * IS2};

    const float4* bw4 = (const float4*)bw;
    float4* o4 = (float4*)(out + ((size_t)b * Sc + 8 * (size_t)g) * Dc);
    float4 b0 = bw4[tid];
    float4 b1 = bw4[512 + tid];
    float4 b2 = bw4[1024 + tid];
    float4 b3 = bw4[1536 + tid];
#pragma unroll
    for (int r = 0; r < 8; r++) {
        float s2 = (r < 4) ? 1.0f : -1.0f;
        float s1 = (((r >> 1) & 1) == 0) ? 1.0f : -1.0f;
        float s0 = ((r & 1) == 0) ? 1.0f : -1.0f;
        float k0 = cA;
        float k1 = s2 * c3;
        float k2 = s1 * c2arr[r >> 2];
        float k3 = s0 * c1arr[r >> 1];
        float4 o;
        o.x = k0 * b0.x + k1 * b1.x + k2 * b2.x + k3 * b3.x;
        o.y = k0 * b0.y + k1 * b1.y + k2 * b2.y + k3 * b3.y;
        o.z = k0 * b0.z + k1 * b1.z + k2 * b2.z + k3 * b3.z;
        o.w = k0 * b0.w + k1 * b1.w + k2 * b2.w + k3 * b3.w;
        o4[r * 512 + tid] = o;
    }
}

// ---------------- init: zero flags/counters each launch ------------------
__global__ void init_kernel() {
    int t = threadIdx.x;
    if (t < 16) g_flags[t] = 0;
    if (t < 2) g_ctr[t] = 0;
}

// ---------------- fused persistent kernel --------------------------------
// bids 0..7: sim CTA per batch (wave-1 resident; spin on prep flag).
// bids 8..295: workers — drain prep tiles, then drain out tiles.
// Grid <= residency, so all CTAs making progress are resident: deadlock-free.
__global__ void __launch_bounds__(NTS, 1) fused_kernel(
        const float* __restrict__ x, const float* __restrict__ wval,
        const float* __restrict__ phi, const float* __restrict__ bw,
        float* __restrict__ out) {
    extern __shared__ float sm[];
    __shared__ int s_t;
    int bid = blockIdx.x;
    int tid = threadIdx.x;

    if (bid < 8) {
        // ---- sim path ----
        if (tid == 0) {
            while (*(volatile int*)&g_flags[bid] != 256) __nanosleep(256);
            __threadfence();
        }
        __syncthreads();
        sim_body(bid, phi, sm);
        __threadfence();
        __syncthreads();
        if (tid == 0) atomicExch(&g_flags[8 + bid], 1);
    } else {
        // ---- worker path: prep tiles ----
        for (;;) {
            if (tid == 0) s_t = atomicAdd(&g_ctr[0], 1);
            __syncthreads();
            int t = s_t;
            if (t >= 2048) break;
            prep_tile(t, x, wval, sm);   // ends with fence+sync+flag
        }
        // ---- worker path: out tiles (batch-major, matches sim order) ----
        for (;;) {
            if (tid == 0) s_t = atomicAdd(&g_ctr[1], 1);
            __syncthreads();
            int t = s_t;
            if (t >= 2048) break;
            if (tid == 0) {
                while (*(volatile int*)&g_flags[8 + (t >> 8)] == 0) __nanosleep(256);
                __threadfence();
            }
            __syncthreads();
            out_tile(t, bw, out);
        }
    }
}

// ---------------- launch --------------------------------------------------
extern "C" void kernel_launch(void* const* d_in, const int* in_sizes, int n_in,
                              void* d_out, int out_size) {
    const float* x    = (const float*)d_in[0];
    const float* wval = (const float*)d_in[1];
    const float* phi  = (const float*)d_in[2];
    const float* bw   = (const float*)d_in[3];
    float* out = (float*)d_out;

    cudaFuncSetAttribute(fused_kernel, cudaFuncAttributeMaxDynamicSharedMemorySize,
                         SIM_SMEM);

    init_kernel<<<1, 32>>>();
    fused_kernel<<<296, NTS, SIM_SMEM>>>(x, wval, phi, bw, out);
}

// round 14
// speedup vs baseline: 1.0772x; 1.0772x over previous
#include <cuda_runtime.h>
#include <math.h>

#define Sc 2048
#define Dc 2048
#define NTS 512
#define FULLM 0xffffffffu
#define IS2 0.70710678118654752440f
#define HAL 72
#define LD 2192

// ---------------- device scratch ----------------------------------------
__device__ float g_ssq[8 * Sc];   // sum over d of dwt coeff^2
__device__ float g_pt[8 * Sc];    // per-token dot with w_val
__device__ float g_rhof[8 * Sc];  // final rho_f (normalized)
__device__ int g_flags[16];       // [0..7] prep tile counts, [8..15] rhof done

__device__ __forceinline__ void pdl_trigger() {
#if defined(__CUDA_ARCH__) && __CUDA_ARCH__ >= 900
    cudaTriggerProgrammaticLaunchCompletion();
#endif
}

// ---------------- compile-time leray taps --------------------------------
struct Taps {
    float k[68];    // leray taps, disp -32..+32 (65 used, pad 68)
    float k2[68];   // 0.0125 * (kl conv kl), disp -32..+32 (65 used, pad 68)
};
__host__ __device__ constexpr Taps make_taps() {
    Taps t = {};
    double p[256] = {};
    double pn[256] = {};
    for (int it = 0; it < 50; it++) {
        for (int i = 0; i < 256; i++) {
            double l = (i > 0) ? p[i - 1] : 0.0;
            double r = (i < 255) ? p[i + 1] : 0.0;
            double bb = (i == 128) ? 1.0 : ((i == 129) ? -1.0 : 0.0);
            pn[i] = 0.5 * (r + l - bb);
        }
        for (int i = 0; i < 256; i++) p[i] = pn[i];
    }
    double kl[103] = {};
    for (int j = 0; j < 103; j++) {
        int i = 77 + j;                      // disp = j - 51
        double del = (i == 128) ? 1.0 : 0.0;
        kl[j] = del - (p[i + 1] - p[i]);
    }
    for (int j = 0; j < 68; j++)
        t.k[j] = (j < 65) ? (float)kl[j + 19] : 0.0f;
    for (int j = 0; j < 68; j++) {
        double s = 0.0;
        if (j < 65) {
            int d = j - 32;
            for (int a = -51; a <= 51; a++) {
                int e = d - a;
                if (e >= -51 && e <= 51) s += kl[a + 51] * kl[e + 51];
            }
            s *= 0.0125;                     // INNER_LR / B folded in
        }
        t.k2[j] = (float)s;
    }
    return t;
}

// ---------------- prep: DWT energies + per-token dots --------------------
__global__ void __launch_bounds__(256) prep_kernel(const float* __restrict__ x,
                                                   const float* __restrict__ wval) {
    pdl_trigger();               // sim may launch; it spins on g_flags anyway
    int g = blockIdx.x;   // 0..255
    int b = blockIdx.y;   // 0..7
    int tid = threadIdx.x;
    const float4* xv = (const float4*)(x + ((size_t)b * Sc + 8 * (size_t)g) * Dc);
    const float4* wv = (const float4*)wval;

    float acc[16];
#pragma unroll
    for (int i = 0; i < 16; i++) acc[i] = 0.0f;

#pragma unroll
    for (int c = 0; c < 2; c++) {
        int c4 = tid + c * 256;
        float4 w4 = wv[c4];
        float xr[4][8];
#pragma unroll
        for (int r = 0; r < 8; r++) {
            float4 q = xv[r * 512 + c4];
            xr[0][r] = q.x; xr[1][r] = q.y; xr[2][r] = q.z; xr[3][r] = q.w;
        }
        float wc[4] = {w4.x, w4.y, w4.z, w4.w};
#pragma unroll
        for (int cc = 0; cc < 4; cc++) {
            const float* X = xr[cc];
            float w = wc[cc];
#pragma unroll
            for (int r = 0; r < 8; r++) acc[8 + r] += X[r] * w;
            float a10 = (X[0] + X[1]) * IS2, d10 = (X[0] - X[1]) * IS2;
            float a11 = (X[2] + X[3]) * IS2, d11 = (X[2] - X[3]) * IS2;
            float a12 = (X[4] + X[5]) * IS2, d12 = (X[4] - X[5]) * IS2;
            float a13 = (X[6] + X[7]) * IS2, d13 = (X[6] - X[7]) * IS2;
            float a20 = (a10 + a11) * IS2, d20 = (a10 - a11) * IS2;
            float a21 = (a12 + a13) * IS2, d21 = (a12 - a13) * IS2;
            float a3 = (a20 + a21) * IS2, d3 = (a20 - a21) * IS2;
            acc[0] += a3 * a3;   acc[1] += d3 * d3;
            acc[2] += d20 * d20; acc[3] += d21 * d21;
            acc[4] += d10 * d10; acc[5] += d11 * d11;
            acc[6] += d12 * d12; acc[7] += d13 * d13;
        }
    }
#pragma unroll
    for (int off = 16; off; off >>= 1)
#pragma unroll
        for (int j = 0; j < 16; j++) acc[j] += __shfl_xor_sync(FULLM, acc[j], off);

    __shared__ float sred[8 * 16];
    int lane = tid & 31, wid = tid >> 5;
    if (lane == 0)
#pragma unroll
        for (int j = 0; j < 16; j++) sred[wid * 16 + j] = acc[j];
    __syncthreads();
    if (tid < 16) {
        float s = 0.0f;
#pragma unroll
        for (int w = 0; w < 8; w++) s += sred[w * 16 + tid];
        int base = b * Sc;
        if (tid < 8) {
            int idx;
            if (tid == 0) idx = g;
            else if (tid == 1) idx = 256 + g;
            else if (tid < 4) idx = 512 + 2 * g + (tid - 2);
            else idx = 1024 + 4 * g + (tid - 4);
            g_ssq[base + idx] = s;
        } else {
            g_pt[base + 8 * g + (tid - 8)] = s;
        }
    }
    __threadfence();
    __syncthreads();
    if (tid == 0) atomicAdd(&g_flags[b], 1);
}

// ---------------- small helpers ------------------------------------------
__device__ __forceinline__ float4 ld4(const float* p) { return *(const float4*)p; }
__device__ __forceinline__ void st4(float* p, float4 v) { *(float4*)p = v; }
__device__ __forceinline__ void st4h(float* A, int i0, float4 v) {
    *(float4*)(A + i0) = v;
    if (i0 < HAL) *(float4*)(A + i0 + Sc) = v;
    if (i0 >= Sc - HAL) *(float4*)(A + i0 - Sc) = v;
}
__device__ __forceinline__ void sth(float* A, int i, float v) {
    A[i] = v;
    if (i < HAL) A[i + Sc] = v;
    if (i >= Sc - HAL) A[i - Sc] = v;
}

// ------------- single-barrier reductions (512 thr, 16 warps) -------------
__device__ __forceinline__ float bsum1(float v, float* red, int& sl) {
#pragma unroll
    for (int o = 16; o; o >>= 1) v += __shfl_xor_sync(FULLM, v, o);
    int lane = threadIdx.x & 31, wid = threadIdx.x >> 5;
    if (lane == 0) red[sl * 16 + wid] = v;
    __syncthreads();
    float s = 0.0f;
    const float* rr = red + sl * 16;
#pragma unroll
    for (int w = 0; w < 16; w++) s += rr[w];
    sl ^= 1;
    return s;
}

__device__ __forceinline__ float bsum2(float v, float v2, float* red, float* red2,
                                       int& sl, float* out2) {
#pragma unroll
    for (int o = 16; o; o >>= 1) {
        v += __shfl_xor_sync(FULLM, v, o);
        v2 += __shfl_xor_sync(FULLM, v2, o);
    }
    int lane = threadIdx.x & 31, wid = threadIdx.x >> 5;
    if (lane == 0) { red[sl * 16 + wid] = v; red2[wid] = v2; }
    __syncthreads();
    float s = 0.0f, s2 = 0.0f;
    const float* rr = red + sl * 16;
#pragma unroll
    for (int w = 0; w < 16; w++) { s += rr[w]; s2 += red2[w]; }
    sl ^= 1;
    *out2 = s2;
    return s;
}

__device__ __forceinline__ void partial_store(float p, float* red, int sl) {
#pragma unroll
    for (int o = 16; o; o >>= 1) p += __shfl_xor_sync(FULLM, p, o);
    int lane = threadIdx.x & 31, wid = threadIdx.x >> 5;
    if (lane == 0) red[sl * 16 + wid] = p;
}
__device__ __forceinline__ float partial_read(const float* red, int& sl) {
    float s = 0.0f;
    const float* rr = red + sl * 16;
#pragma unroll
    for (int w = 0; w < 16; w++) s += rr[w];
    sl ^= 1;
    return s;
}

__device__ __forceinline__ float bmax1(float v, float* mred) {
#pragma unroll
    for (int o = 16; o; o >>= 1) v = fmaxf(v, __shfl_xor_sync(FULLM, v, o));
    int lane = threadIdx.x & 31, wid = threadIdx.x >> 5;
    if (lane == 0) mred[wid] = v;
    __syncthreads();
    float m = mred[0];
#pragma unroll
    for (int w = 1; w < 16; w++) m = fmaxf(m, mred[w]);
    return m;
}

__device__ __forceinline__ float bmaxcnt1(float m, float c, float* mred, float* cnt_out) {
#pragma unroll
    for (int o = 16; o; o >>= 1) {
        float m2 = __shfl_xor_sync(FULLM, m, o);
        float c2 = __shfl_xor_sync(FULLM, c, o);
        if (m2 > m) { m = m2; c = c2; }
        else if (m2 == m) { c += c2; }
    }
    int lane = threadIdx.x & 31, wid = threadIdx.x >> 5;
    if (lane == 0) { mred[wid] = m; mred[16 + wid] = c; }
    __syncthreads();
    float M = mred[0];
#pragma unroll
    for (int w = 1; w < 16; w++) M = fmaxf(M, mred[w]);
    float C = 0.0f;
#pragma unroll
    for (int w = 0; w < 16; w++) C += (mred[w] == M) ? mred[16 + w] : 0.0f;
    *cnt_out = C;
    return M;
}

// ---------------- leray: 65-tap conv, immediate taps (init only) ---------
__device__ __forceinline__ void conv_leray(float* __restrict__ dst,
                                           const float* __restrict__ src) {
    constexpr Taps TAPS = make_taps();
    int i0 = 4 * threadIdx.x;
    const float* S = src + i0 - 32;
    float4 cur = ld4(S);
    float a0 = 0.0f, a1 = 0.0f, a2 = 0.0f, a3 = 0.0f;
#pragma unroll
    for (int m = 0; m < 17; m++) {
        float4 nxt = ld4(S + 4 * m + 4);
        const float kx = TAPS.k[4 * m], ky = TAPS.k[4 * m + 1];
        const float kz = TAPS.k[4 * m + 2], kw = TAPS.k[4 * m + 3];
        a0 += kx * cur.x + ky * cur.y + kz * cur.z + kw * cur.w;
        a1 += kx * cur.y + ky * cur.z + kz * cur.w + kw * nxt.x;
        a2 += kx * cur.z + ky * cur.w + kz * nxt.x + kw * nxt.y;
        a3 += kx * cur.w + ky * nxt.x + kz * nxt.y + kw * nxt.z;
        cur = nxt;
    }
    st4h(dst, i0, make_float4(a0, a1, a2, a3));
    __syncthreads();
}

// ------- fused: up -= (lr/B)*leray^2(ub), 65-tap imm conv, no barrier ----
__device__ __forceinline__ void conv2_update(float* __restrict__ up,
                                             const float* __restrict__ ub) {
    constexpr Taps TAPS = make_taps();
    int i0 = 4 * threadIdx.x;
    const float* S = ub + i0 - 32;
    float4 cur = ld4(S);
    float a0 = 0.0f, a1 = 0.0f, a2 = 0.0f, a3 = 0.0f;
#pragma unroll
    for (int m = 0; m < 17; m++) {
        float4 nxt = ld4(S + 4 * m + 4);
        const float kx = TAPS.k2[4 * m], ky = TAPS.k2[4 * m + 1];
        const float kz = TAPS.k2[4 * m + 2], kw = TAPS.k2[4 * m + 3];
        a0 += kx * cur.x + ky * cur.y + kz * cur.z + kw * cur.w;
        a1 += kx * cur.y + ky * cur.z + kz * cur.w + kw * nxt.x;
        a2 += kx * cur.z + ky * cur.w + kz * nxt.x + kw * nxt.y;
        a3 += kx * cur.w + ky * nxt.x + kz * nxt.y + kw * nxt.z;
        cur = nxt;
    }
    float4 u = ld4(up + i0);
    st4h(up, i0, make_float4(u.x - a0, u.y - a1, u.z - a2, u.w - a3));
}

// ---- forward advect: store RAW y, one barrier, return Z -----------------
__device__ __forceinline__ float advect_fwd(float* __restrict__ dst,
                                            const float* __restrict__ r, float iZr,
                                            const float uv[5],
                                            float dt, float* red, int& sl) {
    int i0 = 4 * threadIdx.x;
    float4 r0 = ld4(r + i0);
    float rv[6] = {r[i0 - 1] * iZr, r0.x * iZr, r0.y * iZr, r0.z * iZr, r0.w * iZr,
                   r[i0 + 4] * iZr};
    float F[5];
#pragma unroll
    for (int k = 0; k < 5; k++)
        F[k] = uv[k] > 0.0f ? uv[k] * rv[k] : uv[k] * rv[k + 1];
    float y[4], part = 0.0f;
#pragma unroll
    for (int e = 0; e < 4; e++) {
        y[e] = fabsf(rv[e + 1] - dt * (F[e + 1] - F[e])) + 1e-8f;
        part += y[e];
    }
    st4h(dst, i0, make_float4(y[0], y[1], y[2], y[3]));
    return bsum1(part, red, sl);
}

// ---- forward advect for r4: also reduces dot((1-v), y_raw) --------------
__device__ __forceinline__ float advect_fwd_dot(float* __restrict__ dst,
                                                const float* __restrict__ r, float iZr,
                                                const float uv[5],
                                                const float* __restrict__ vA,
                                                float dt, float* red, float* red2,
                                                int& sl, float* dotraw_out) {
    int i0 = 4 * threadIdx.x;
    float4 r0 = ld4(r + i0);
    float rv[6] = {r[i0 - 1] * iZr, r0.x * iZr, r0.y * iZr, r0.z * iZr, r0.w * iZr,
                   r[i0 + 4] * iZr};
    float F[5];
#pragma unroll
    for (int k = 0; k < 5; k++)
        F[k] = uv[k] > 0.0f ? uv[k] * rv[k] : uv[k] * rv[k + 1];
    float4 v4 = ld4(vA + i0);
    float vb[4] = {1.0f - v4.x, 1.0f - v4.y, 1.0f - v4.z, 1.0f - v4.w};
    float y[4], part = 0.0f, part2 = 0.0f;
#pragma unroll
    for (int e = 0; e < 4; e++) {
        y[e] = fabsf(rv[e + 1] - dt * (F[e + 1] - F[e])) + 1e-8f;
        part += y[e];
        part2 += vb[e] * y[e];
    }
    st4h(dst, i0, make_float4(y[0], y[1], y[2], y[3]));
    return bsum2(part, part2, red, red2, sl, dotraw_out);
}

// ---- final outer advect (with kappa), stores NORMALIZED -----------------
__device__ __forceinline__ void advect_final(float* __restrict__ dst,
                                             const float* __restrict__ r,
                                             const float* __restrict__ u,
                                             float dt, float kap, float* red, int& sl) {
    int i0 = 4 * threadIdx.x;
    float4 r0 = ld4(r + i0);
    float rv[6] = {r[i0 - 1], r0.x, r0.y, r0.z, r0.w, r[i0 + 4]};
    float4 u0 = ld4(u + i0);
    float uv[5] = {u[i0 - 1], u0.x, u0.y, u0.z, u0.w};
    float F[5];
#pragma unroll
    for (int k = 0; k < 5; k++)
        F[k] = uv[k] > 0.0f ? uv[k] * rv[k] : uv[k] * rv[k + 1];
    float y[4], part = 0.0f;
#pragma unroll
    for (int e = 0; e < 4; e++) {
        float a = rv[e + 1] - dt * (F[e + 1] - F[e])
                + kap * dt * (rv[e + 2] + rv[e] - 2.0f * rv[e + 1]);
        y[e] = fabsf(a) + 1e-8f;
        part += y[e];
    }
    float Z = bsum1(part, red, sl);
    float iZ = 1.0f / Z;
    st4h(dst, i0, make_float4(y[0] * iZ, y[1] * iZ, y[2] * iZ, y[3] * iZ));
}

// ---- FIRST backward step (t=4): rb=(1-v), dot from fwd; SETS ub ---------
__device__ __forceinline__ float bwd_first(const float* __restrict__ rt, float iZt,
                                           float Zn, float dotraw,
                                           const float uv[5], float dt,
                                           const float* __restrict__ vA,
                                           float* __restrict__ abA,
                                           float rb[4], float ub[4],
                                           float* red, int sl) {
    int i0 = 4 * threadIdx.x;
    float iZn = 1.0f / Zn;
    float dot = dotraw * iZn;

    float4 r0 = ld4(rt + i0);
    float rr[4] = {r0.x, r0.y, r0.z, r0.w};
    float rv[6] = {rt[i0 - 1] * iZt, r0.x * iZt, r0.y * iZt, r0.z * iZt, r0.w * iZt,
                   rt[i0 + 4] * iZt};
    float F[5];
#pragma unroll
    for (int k = 0; k < 5; k++)
        F[k] = uv[k] > 0.0f ? uv[k] * rv[k] : uv[k] * rv[k + 1];

    float4 v4 = ld4(vA + i0);
    float rbl[4] = {1.0f - v4.x, 1.0f - v4.y, 1.0f - v4.z, 1.0f - v4.w};
    float ab[4], dtl = 0.0f;
#pragma unroll
    for (int e = 0; e < 4; e++) {
        float a = rv[e + 1] - dt * (F[e + 1] - F[e]);
        float s = (a > 0.0f) ? 1.0f : ((a < 0.0f) ? -1.0f : 0.0f);
        ab[e] = (rbl[e] - dot) * iZn * s;
        dtl -= ab[e] * (F[e + 1] - F[e]);
    }
    st4h(abA, i0, make_float4(ab[0], ab[1], ab[2], ab[3]));
    __syncthreads();

    float abv[6] = {abA[i0 - 1], ab[0], ab[1], ab[2], ab[3], abA[i0 + 4]};
    float Fb[5];
#pragma unroll
    for (int k = 0; k < 5; k++)
        Fb[k] = -dt * (abv[k] - abv[k + 1]);
#pragma unroll
    for (int e = 0; e < 4; e++) {
        ub[e] = Fb[e + 1] * (uv[e + 1] > 0.0f ? rv[e + 1] : rv[e + 2]);
        rb[e] = ab[e] + (uv[e + 1] > 0.0f ? Fb[e + 1] * uv[e + 1] : 0.0f)
                      + (uv[e] > 0.0f ? 0.0f : Fb[e] * uv[e]);
    }
    partial_store(rb[0] * rr[0] + rb[1] * rr[1] + rb[2] * rr[2] + rb[3] * rr[3],
                  red, sl);
    return dtl;
}

// ---- middle backward step: entry barrier publishes the pending partial --
__device__ __forceinline__ float bwd_mid(const float* __restrict__ rt, float iZt,
                                         float Zn,
                                         const float uv[5], float dt,
                                         float* __restrict__ abA,
                                         float rb[4], float ub[4],
                                         float* red, int& sl) {
    int i0 = 4 * threadIdx.x;
    __syncthreads();
    float dotraw = partial_read(red, sl);
    float iZn = 1.0f / Zn;
    float dot = dotraw * iZn;

    float4 r0 = ld4(rt + i0);
    float rr[4] = {r0.x, r0.y, r0.z, r0.w};
    float rv[6] = {rt[i0 - 1] * iZt, r0.x * iZt, r0.y * iZt, r0.z * iZt, r0.w * iZt,
                   rt[i0 + 4] * iZt};
    float F[5];
#pragma unroll
    for (int k = 0; k < 5; k++)
        F[k] = uv[k] > 0.0f ? uv[k] * rv[k] : uv[k] * rv[k + 1];

    float ab[4], dtl = 0.0f;
#pragma unroll
    for (int e = 0; e < 4; e++) {
        float a = rv[e + 1] - dt * (F[e + 1] - F[e]);
        float s = (a > 0.0f) ? 1.0f : ((a < 0.0f) ? -1.0f : 0.0f);
        ab[e] = (rb[e] - dot) * iZn * s;
        dtl -= ab[e] * (F[e + 1] - F[e]);
    }
    st4h(abA, i0, make_float4(ab[0], ab[1], ab[2], ab[3]));
    __syncthreads();

    float abv[6] = {abA[i0 - 1], ab[0], ab[1], ab[2], ab[3], abA[i0 + 4]};
    float Fb[5];
#pragma unroll
    for (int k = 0; k < 5; k++)
        Fb[k] = -dt * (abv[k] - abv[k + 1]);
#pragma unroll
    for (int e = 0; e < 4; e++) {
        ub[e] += Fb[e + 1] * (uv[e + 1] > 0.0f ? rv[e + 1] : rv[e + 2]);
        rb[e] = ab[e] + (uv[e + 1] > 0.0f ? Fb[e + 1] * uv[e + 1] : 0.0f)
                      + (uv[e] > 0.0f ? 0.0f : Fb[e] * uv[e]);
    }
    partial_store(rb[0] * rr[0] + rb[1] * rr[1] + rb[2] * rr[2] + rb[3] * rr[3],
                  red, sl);
    return dtl;
}

// ---- LAST backward step: dtbar fused into the abA-publish barrier -------
__device__ __forceinline__ float bwd_last(const float* __restrict__ rt,
                                          float Zn,
                                          const float uv[5], float dt, float dtl_in,
                                          float* __restrict__ abA,
                                          float rb[4], float ub[4],
                                          float* red, float* red2, int& sl) {
    int i0 = 4 * threadIdx.x;
    __syncthreads();
    float dotraw = partial_read(red, sl);
    float iZn = 1.0f / Zn;
    float dot = dotraw * iZn;

    float4 r0 = ld4(rt + i0);
    float rv[6] = {rt[i0 - 1], r0.x, r0.y, r0.z, r0.w, rt[i0 + 4]};  // iZt = 1
    float F[5];
#pragma unroll
    for (int k = 0; k < 5; k++)
        F[k] = uv[k] > 0.0f ? uv[k] * rv[k] : uv[k] * rv[k + 1];

    float ab[4], dtl = dtl_in;
#pragma unroll
    for (int e = 0; e < 4; e++) {
        float a = rv[e + 1] - dt * (F[e + 1] - F[e]);
        float s = (a > 0.0f) ? 1.0f : ((a < 0.0f) ? -1.0f : 0.0f);
        ab[e] = (rb[e] - dot) * iZn * s;
        dtl -= ab[e] * (F[e + 1] - F[e]);
    }
    st4h(abA, i0, make_float4(ab[0], ab[1], ab[2], ab[3]));
    float t = dtl;
#pragma unroll
    for (int o = 16; o; o >>= 1) t += __shfl_xor_sync(FULLM, t, o);
    int lane = threadIdx.x & 31, wid = threadIdx.x >> 5;
    if (lane == 0) red2[wid] = t;
    __syncthreads();
    float dtbar = 0.0f;
#pragma unroll
    for (int w = 0; w < 16; w++) dtbar += red2[w];

    float abv[6] = {abA[i0 - 1], ab[0], ab[1], ab[2], ab[3], abA[i0 + 4]};
    float Fb[5];
#pragma unroll
    for (int k = 0; k < 5; k++)
        Fb[k] = -dt * (abv[k] - abv[k + 1]);
#pragma unroll
    for (int e = 0; e < 4; e++)
        ub[e] += Fb[e + 1] * (uv[e + 1] > 0.0f ? rv[e + 1] : rv[e + 2]);
    return dtbar;
}

// ---------------- sim body: one CTA, batch b -----------------------------
#define SIM_SMEM ((2128 + 11 * LD) * 4)

__device__ void sim_body(int b, const float* __restrict__ phi_g, float* sm) {
    float* red  = sm;          // 32 (2 slots x 16)
    float* red2 = sm + 32;     // 16
    float* mred = sm + 48;     // 32
    float* phiA = sm + 80;     // 2048
    float* arr  = sm + 2128;   // 11 x LD haloed arrays
    float* vA   = arr + 0 * LD + HAL;
    float* up0A = arr + 1 * LD + HAL;
    float* upA  = arr + 2 * LD + HAL;
    float* rhoA = arr + 3 * LD + HAL;
    float* spA  = arr + 4 * LD + HAL;
    float* r1A  = arr + 5 * LD + HAL;
    float* r2A  = arr + 6 * LD + HAL;
    float* r3A  = arr + 7 * LD + HAL;
    float* r4A  = arr + 8 * LD + HAL;
    float* abA  = arr + 9 * LD + HAL;
    float* ubA  = arr + 10 * LD + HAL;

    int tid = threadIdx.x;
    int i0 = 4 * tid;
    int sl = 0;

    st4(phiA + i0, ld4(phi_g + i0));

    {
        float4 s4 = ld4(g_ssq + b * Sc + i0);
        float y0 = sqrtf(s4.x) + 1e-8f, y1 = sqrtf(s4.y) + 1e-8f;
        float y2 = sqrtf(s4.z) + 1e-8f, y3 = sqrtf(s4.w) + 1e-8f;
        float Z = bsum1(y0 + y1 + y2 + y3, red, sl);
        float iZ = 1.0f / Z;
        st4h(rhoA, i0, make_float4(y0 * iZ, y1 * iZ, y2 * iZ, y3 * iZ));
    }

    st4(r1A + i0, ld4(g_pt + b * Sc + i0));
    __syncthreads();
#pragma unroll
    for (int s = 0; s < 2; s++) {           // level 1
        int j = 2 * tid + s;
        float e = r1A[2 * j], o = r1A[2 * j + 1];
        sth(vA, 1024 + j, (e - o) * IS2);
        r2A[j] = (e + o) * IS2;
    }
    __syncthreads();
    {                                       // level 2
        float e = r2A[2 * tid], o = r2A[2 * tid + 1];
        sth(vA, 512 + tid, (e - o) * IS2);
        r1A[tid] = (e + o) * IS2;
    }
    __syncthreads();
    if (tid < 256) {                        // level 3
        float e = r1A[2 * tid], o = r1A[2 * tid + 1];
        sth(vA, 256 + tid, (e - o) * IS2);
        sth(vA, tid, (e + o) * IS2);
    }
    __syncthreads();
    {
        float4 v4 = ld4(vA + i0);
        float y0 = 45.254833995939045f * fabsf(v4.x) + 1e-8f;
        float y1 = 45.254833995939045f * fabsf(v4.y) + 1e-8f;
        float y2 = 45.254833995939045f * fabsf(v4.z) + 1e-8f;
        float y3 = 45.254833995939045f * fabsf(v4.w) + 1e-8f;
        float Z = bsum1(y0 + y1 + y2 + y3, red, sl);
        float iZ = 1.0f / Z;
        st4h(vA, i0, make_float4(y0 * iZ, y1 * iZ, y2 * iZ, y3 * iZ));
        __syncthreads();
    }

    {
        float4 v0 = ld4(vA + i0);
        float v4n = vA[i0 + 4];
        st4h(ubA, i0, make_float4(v0.y - v0.x, v0.z - v0.y, v0.w - v0.z, v4n - v0.w));
        __syncthreads();
        conv_leray(up0A, ubA);
    }

    float* rho = rhoA;
    float* spare = spA;

#pragma unroll 1
    for (int k = 0; k < 3; k++) {
        float kap = (k == 0) ? 0.01f : ((k == 1) ? 0.005f : 0.0f);

        for (int q = 4 * tid; q < LD; q += 4 * NTS)
            st4(arr + 2 * LD + q, ld4(arr + 1 * LD + q));

        {
            float4 rh = ld4(rho + i0);
            float4 ph = ld4(phiA + i0);
            float w0 = fabsf(rh.x * expf(-0.1f * (ph.x + logf(rh.x)))) + 1e-8f;
            float w1 = fabsf(rh.y * expf(-0.1f * (ph.y + logf(rh.y)))) + 1e-8f;
            float w2 = fabsf(rh.z * expf(-0.1f * (ph.z + logf(rh.z)))) + 1e-8f;
            float w3 = fabsf(rh.w * expf(-0.1f * (ph.w + logf(rh.w)))) + 1e-8f;
            float Z = bsum1(w0 + w1 + w2 + w3, red, sl);
            float iZ = 1.0f / Z;
            st4h(rho, i0, make_float4(w0 * iZ, w1 * iZ, w2 * iZ, w3 * iZ));
        }

#pragma unroll 1
        for (int is = 0; is < 5; is++) {
            float4 up4 = ld4(upA + i0);
            float a0 = fabsf(up4.x), a1 = fabsf(up4.y);
            float a2 = fabsf(up4.z), a3 = fabsf(up4.w);
            float lm = fmaxf(fmaxf(a0, a1), fmaxf(a2, a3));
            float lc = (a0 == lm ? 1.0f : 0.0f) + (a1 == lm ? 1.0f : 0.0f)
                     + (a2 == lm ? 1.0f : 0.0f) + (a3 == lm ? 1.0f : 0.0f);
            float nt;
            float m = bmaxcnt1(lm, lc, mred, &nt);
            float dt = 0.4f / (m + 1e-8f);

            float uv[5] = {upA[i0 - 1], up4.x, up4.y, up4.z, up4.w};

            float z0 = advect_fwd(r1A, rho, 1.0f, uv, dt, red, sl);
            float z1 = advect_fwd(r2A, r1A, 1.0f / z0, uv, dt, red, sl);
            float z2 = advect_fwd(r3A, r2A, 1.0f / z1, uv, dt, red, sl);
            float dotraw;
            float z3 = advect_fwd_dot(r4A, r3A, 1.0f / z2, uv, vA, dt,
                                      red, red2, sl, &dotraw);

            float rb[4], ub[4];
            float dtl = bwd_first(r3A, 1.0f / z2, z3, dotraw, uv, dt,
                                  vA, abA, rb, ub, red, sl);
            dtl += bwd_mid(r2A, 1.0f / z1, z2, uv, dt, abA, rb, ub, red, sl);
            dtl += bwd_mid(r1A, 1.0f / z0, z1, uv, dt, abA, rb, ub, red, sl);
            float dtbar = bwd_last(rho, z0, uv, dt, dtl, abA, rb, ub,
                                   red, red2, sl);

            float mbar = dtbar * (-dt * dt * 2.5f);
            {
                float inv_nt = mbar / nt;
                ub[0] += (a0 == m) ? inv_nt * ((up4.x > 0.0f) ? 1.0f : -1.0f) : 0.0f;
                ub[1] += (a1 == m) ? inv_nt * ((up4.y > 0.0f) ? 1.0f : -1.0f) : 0.0f;
                ub[2] += (a2 == m) ? inv_nt * ((up4.z > 0.0f) ? 1.0f : -1.0f) : 0.0f;
                ub[3] += (a3 == m) ? inv_nt * ((up4.w > 0.0f) ? 1.0f : -1.0f) : 0.0f;
                st4h(ubA, i0, make_float4(ub[0], ub[1], ub[2], ub[3]));
            }
            __syncthreads();

            conv2_update(upA, ubA);
        }

        {
            float4 up4 = ld4(upA + i0);
            float lm = fmaxf(fmaxf(fabsf(up4.x), fabsf(up4.y)),
                             fmaxf(fabsf(up4.z), fabsf(up4.w)));
            float mm = bmax1(lm, mred);
            float dt = 0.4f / (mm + 1e-8f);
            advect_final(spare, rho, upA, dt, kap, red, sl);
            float* tmp = rho; rho = spare; spare = tmp;
        }
    }

    {
        float4 rh = ld4(rho + i0);
        float4 v4 = ld4(vA + i0);
        float f0 = rh.x + 0.1f * v4.x, f1 = rh.y + 0.1f * v4.y;
        float f2 = rh.z + 0.1f * v4.z, f3 = rh.w + 0.1f * v4.w;
        float Z = bsum1(f0 + f1 + f2 + f3, red, sl);
        float iZ = 1.0f / Z;
        st4(g_rhof + b * Sc + i0, make_float4(f0 * iZ, f1 * iZ, f2 * iZ, f3 * iZ));
    }
}

// ---------------- sim kernel: spin on prep flags, signal done ------------
__global__ void __launch_bounds__(NTS, 1) sim_kernel(const float* __restrict__ phi) {
    extern __shared__ float sm[];
    pdl_trigger();     // out_kernel dispatches only after ALL 8 sims placed
    int b = blockIdx.x;
    if (threadIdx.x == 0) {
        while (*(volatile int*)&g_flags[b] != 256) __nanosleep(256);
        __threadfence();
    }
    __syncthreads();
    sim_body(b, phi, sm);
    __threadfence();
    __syncthreads();
    if (threadIdx.x == 0) atomicExch(&g_flags[8 + b], 1);
}

// ---------------- out: spin per-batch, then fused inverse DWT ------------
__global__ void __launch_bounds__(256) out_kernel(const float* __restrict__ bw,
                                                  float* __restrict__ out) {
    int g = blockIdx.x, b = blockIdx.y, tid = threadIdx.x;
    if (tid == 0) {
        while (*(volatile int*)&g_flags[8 + b] == 0) __nanosleep(256);
        __threadfence();
    }
    __syncthreads();

    const float* rf = g_rhof + b * Sc;
    float rfA = rf[g];
    float rf3 = rf[256 + g];
    float rf2a = rf[512 + 2 * g], rf2b = rf[512 + 2 * g + 1];
    float rf1_0 = rf[1024 + 4 * g], rf1_1 = rf[1024 + 4 * g + 1];
    float rf1_2 = rf[1024 + 4 * g + 2], rf1_3 = rf[1024 + 4 * g + 3];

    const float C8 = 0.35355339059327376220f;
    float cA = rfA * C8;
    float c3 = rf3 * C8;
    float c2arr[2] = {rf2a * 0.5f, rf2b * 0.5f};
    float c1arr[4] = {rf1_0 * IS2, rf1_1 * IS2, rf1_2 * IS2, rf1_3 * IS2};

    const float4* bw4 = (const float4*)bw;
    float4* o4 = (float4*)(out + ((size_t)b * Sc + 8 * (size_t)g) * Dc);
#pragma unroll
    for (int c = 0; c < 2; c++) {
        int c4 = tid + c * 256;
        float4 b0 = bw4[0 * 512 + c4];
        float4 b1 = bw4[1 * 512 + c4];
        float4 b2 = bw4[2 * 512 + c4];
        float4 b3 = bw4[3 * 512 + c4];
#pragma unroll
        for (int r = 0; r < 8; r++) {
            float s2 = (r < 4) ? 1.0f : -1.0f;
            float s1 = (((r >> 1) & 1) == 0) ? 1.0f : -1.0f;
            float s0 = ((r & 1) == 0) ? 1.0f : -1.0f;
            float k0 = cA;
            float k1 = s2 * c3;
            float k2 = s1 * c2arr[r >> 2];
            float k3 = s0 * c1arr[r >> 1];
            float4 o;
            o.x = k0 * b0.x + k1 * b1.x + k2 * b2.x + k3 * b3.x;
            o.y = k0 * b0.y + k1 * b1.y + k2 * b2.y + k3 * b3.y;
            o.z = k0 * b0.z + k1 * b1.z + k2 * b2.z + k3 * b3.z;
            o.w = k0 * b0.w + k1 * b1.w + k2 * b2.w + k3 * b3.w;
            o4[r * 512 + c4] = o;
        }
    }
}

// ---------------- init: zero flags each launch ---------------------------
__global__ void init_kernel() {
    if (threadIdx.x < 16) g_flags[threadIdx.x] = 0;
}

// ---------------- launch --------------------------------------------------
extern "C" void kernel_launch(void* const* d_in, const int* in_sizes, int n_in,
                              void* d_out, int out_size) {
    const float* x    = (const float*)d_in[0];
    const float* wval = (const float*)d_in[1];
    const float* phi  = (const float*)d_in[2];
    const float* bw   = (const float*)d_in[3];
    float* out = (float*)d_out;

    cudaFuncSetAttribute(sim_kernel, cudaFuncAttributeMaxDynamicSharedMemorySize,
                         SIM_SMEM);

    init_kernel<<<1, 32>>>();
    prep_kernel<<<dim3(256, 8), 256>>>(x, wval);

    // sim: PDL-dependent on prep (prep triggers at entry; sims spin on flags)
    {
        cudaLaunchConfig_t cfg = {};
        cfg.gridDim = dim3(8);
        cfg.blockDim = dim3(NTS);
        cfg.dynamicSmemBytes = SIM_SMEM;
        cfg.stream = 0;
        cudaLaunchAttribute at[1];
        at[0].id = cudaLaunchAttributeProgrammaticStreamSerialization;
        at[0].val.programmaticStreamSerializationAllowed = 1;
        cfg.attrs = at;
        cfg.numAttrs = 1;
        cudaLaunchKernelEx(&cfg, sim_kernel, phi);
    }

    // out: PDL-dependent on sim (sim triggers at entry => all 8 sims are
    // placed before any out CTA dispatches; out CTAs spin on done flags)
    {
        cudaLaunchConfig_t cfg = {};
        cfg.gridDim = dim3(256, 8);
        cfg.blockDim = dim3(256);
        cfg.dynamicSmemBytes = 0;
        cfg.stream = 0;
        cudaLaunchAttribute at[1];
        at[0].id = cudaLaunchAttributeProgrammaticStreamSerialization;
        at[0].val.programmaticStreamSerializationAllowed = 1;
        cfg.attrs = at;
        cfg.numAttrs = 1;
        cudaLaunchKernelEx(&cfg, out_kernel, bw, out);
    }
}

// round 15
// speedup vs baseline: 1.0779x; 1.0007x over previous
#include <cuda_runtime.h>
#include <math.h>

#define Sc 2048
#define Dc 2048
#define NTS 512
#define FULLM 0xffffffffu
#define IS2 0.70710678118654752440f
#define HAL 72
#define LD 2192

// ---------------- device scratch ----------------------------------------
__device__ float g_ssq[8 * Sc];   // sum over d of dwt coeff^2
__device__ float g_pt[8 * Sc];    // per-token dot with w_val
__device__ float g_rhof[8 * Sc];  // final rho_f (normalized)
__device__ int g_flags[16];       // [0..7] prep tile counts, [8..15] rhof done

__device__ __forceinline__ void pdl_trigger() {
#if defined(__CUDA_ARCH__) && __CUDA_ARCH__ >= 900
    cudaTriggerProgrammaticLaunchCompletion();
#endif
}

// ---------------- compile-time leray taps --------------------------------
struct Taps {
    float k[68];    // leray taps, disp -32..+32 (65 used, pad 68)
    float k2[68];   // 0.0125 * (kl conv kl), disp -32..+32 (65 used, pad 68)
};
__host__ __device__ constexpr Taps make_taps() {
    Taps t = {};
    double p[256] = {};
    double pn[256] = {};
    for (int it = 0; it < 50; it++) {
        for (int i = 0; i < 256; i++) {
            double l = (i > 0) ? p[i - 1] : 0.0;
            double r = (i < 255) ? p[i + 1] : 0.0;
            double bb = (i == 128) ? 1.0 : ((i == 129) ? -1.0 : 0.0);
            pn[i] = 0.5 * (r + l - bb);
        }
        for (int i = 0; i < 256; i++) p[i] = pn[i];
    }
    double kl[103] = {};
    for (int j = 0; j < 103; j++) {
        int i = 77 + j;                      // disp = j - 51
        double del = (i == 128) ? 1.0 : 0.0;
        kl[j] = del - (p[i + 1] - p[i]);
    }
    for (int j = 0; j < 68; j++)
        t.k[j] = (j < 65) ? (float)kl[j + 19] : 0.0f;
    for (int j = 0; j < 68; j++) {
        double s = 0.0;
        if (j < 65) {
            int d = j - 32;
            for (int a = -51; a <= 51; a++) {
                int e = d - a;
                if (e >= -51 && e <= 51) s += kl[a + 51] * kl[e + 51];
            }
            s *= 0.0125;                     // INNER_LR / B folded in
        }
        t.k2[j] = (float)s;
    }
    return t;
}

// ---------------- prep: DWT energies + per-token dots --------------------
__global__ void __launch_bounds__(256) prep_kernel(const float* __restrict__ x,
                                                   const float* __restrict__ wval) {
    pdl_trigger();               // sim may launch; it spins on g_flags anyway
    int g = blockIdx.x;   // 0..255
    int b = blockIdx.y;   // 0..7
    int tid = threadIdx.x;
    const float4* xv = (const float4*)(x + ((size_t)b * Sc + 8 * (size_t)g) * Dc);
    const float4* wv = (const float4*)wval;

    float acc[16];
#pragma unroll
    for (int i = 0; i < 16; i++) acc[i] = 0.0f;

#pragma unroll
    for (int c = 0; c < 2; c++) {
        int c4 = tid + c * 256;
        float4 w4 = wv[c4];
        float xr[4][8];
#pragma unroll
        for (int r = 0; r < 8; r++) {
            float4 q = xv[r * 512 + c4];
            xr[0][r] = q.x; xr[1][r] = q.y; xr[2][r] = q.z; xr[3][r] = q.w;
        }
        float wc[4] = {w4.x, w4.y, w4.z, w4.w};
#pragma unroll
        for (int cc = 0; cc < 4; cc++) {
            const float* X = xr[cc];
            float w = wc[cc];
#pragma unroll
            for (int r = 0; r < 8; r++) acc[8 + r] += X[r] * w;
            float a10 = (X[0] + X[1]) * IS2, d10 = (X[0] - X[1]) * IS2;
            float a11 = (X[2] + X[3]) * IS2, d11 = (X[2] - X[3]) * IS2;
            float a12 = (X[4] + X[5]) * IS2, d12 = (X[4] - X[5]) * IS2;
            float a13 = (X[6] + X[7]) * IS2, d13 = (X[6] - X[7]) * IS2;
            float a20 = (a10 + a11) * IS2, d20 = (a10 - a11) * IS2;
            float a21 = (a12 + a13) * IS2, d21 = (a12 - a13) * IS2;
            float a3 = (a20 + a21) * IS2, d3 = (a20 - a21) * IS2;
            acc[0] += a3 * a3;   acc[1] += d3 * d3;
            acc[2] += d20 * d20; acc[3] += d21 * d21;
            acc[4] += d10 * d10; acc[5] += d11 * d11;
            acc[6] += d12 * d12; acc[7] += d13 * d13;
        }
    }
#pragma unroll
    for (int off = 16; off; off >>= 1)
#pragma unroll
        for (int j = 0; j < 16; j++) acc[j] += __shfl_xor_sync(FULLM, acc[j], off);

    __shared__ float sred[8 * 16];
    int lane = tid & 31, wid = tid >> 5;
    if (lane == 0)
#pragma unroll
        for (int j = 0; j < 16; j++) sred[wid * 16 + j] = acc[j];
    __syncthreads();
    if (tid < 16) {
        float s = 0.0f;
#pragma unroll
        for (int w = 0; w < 8; w++) s += sred[w * 16 + tid];
        int base = b * Sc;
        if (tid < 8) {
            int idx;
            if (tid == 0) idx = g;
            else if (tid == 1) idx = 256 + g;
            else if (tid < 4) idx = 512 + 2 * g + (tid - 2);
            else idx = 1024 + 4 * g + (tid - 4);
            g_ssq[base + idx] = s;
        } else {
            g_pt[base + 8 * g + (tid - 8)] = s;
        }
    }
    __threadfence();
    __syncthreads();
    if (tid == 0) atomicAdd(&g_flags[b], 1);
}

// ---------------- small helpers ------------------------------------------
__device__ __forceinline__ float4 ld4(const float* p) { return *(const float4*)p; }
__device__ __forceinline__ void st4(float* p, float4 v) { *(float4*)p = v; }
__device__ __forceinline__ void st4h(float* A, int i0, float4 v) {
    *(float4*)(A + i0) = v;
    if (i0 < HAL) *(float4*)(A + i0 + Sc) = v;
    if (i0 >= Sc - HAL) *(float4*)(A + i0 - Sc) = v;
}
__device__ __forceinline__ void sth(float* A, int i, float v) {
    A[i] = v;
    if (i < HAL) A[i + Sc] = v;
    if (i >= Sc - HAL) A[i - Sc] = v;
}

// ------------- single-barrier reductions (512 thr, 16 warps) -------------
__device__ __forceinline__ float bsum1(float v, float* red, int& sl) {
#pragma unroll
    for (int o = 16; o; o >>= 1) v += __shfl_xor_sync(FULLM, v, o);
    int lane = threadIdx.x & 31, wid = threadIdx.x >> 5;
    if (lane == 0) red[sl * 16 + wid] = v;
    __syncthreads();
    float s = 0.0f;
    const float* rr = red + sl * 16;
#pragma unroll
    for (int w = 0; w < 16; w++) s += rr[w];
    sl ^= 1;
    return s;
}

__device__ __forceinline__ float bsum2(float v, float v2, float* red, float* red2,
                                       int& sl, float* out2) {
#pragma unroll
    for (int o = 16; o; o >>= 1) {
        v += __shfl_xor_sync(FULLM, v, o);
        v2 += __shfl_xor_sync(FULLM, v2, o);
    }
    int lane = threadIdx.x & 31, wid = threadIdx.x >> 5;
    if (lane == 0) { red[sl * 16 + wid] = v; red2[wid] = v2; }
    __syncthreads();
    float s = 0.0f, s2 = 0.0f;
    const float* rr = red + sl * 16;
#pragma unroll
    for (int w = 0; w < 16; w++) { s += rr[w]; s2 += red2[w]; }
    sl ^= 1;
    *out2 = s2;
    return s;
}

__device__ __forceinline__ void partial_store(float p, float* red, int sl) {
#pragma unroll
    for (int o = 16; o; o >>= 1) p += __shfl_xor_sync(FULLM, p, o);
    int lane = threadIdx.x & 31, wid = threadIdx.x >> 5;
    if (lane == 0) red[sl * 16 + wid] = p;
}
__device__ __forceinline__ float partial_read(const float* red, int& sl) {
    float s = 0.0f;
    const float* rr = red + sl * 16;
#pragma unroll
    for (int w = 0; w < 16; w++) s += rr[w];
    sl ^= 1;
    return s;
}

__device__ __forceinline__ float bmax1(float v, float* mred) {
#pragma unroll
    for (int o = 16; o; o >>= 1) v = fmaxf(v, __shfl_xor_sync(FULLM, v, o));
    int lane = threadIdx.x & 31, wid = threadIdx.x >> 5;
    if (lane == 0) mred[wid] = v;
    __syncthreads();
    float m = mred[0];
#pragma unroll
    for (int w = 1; w < 16; w++) m = fmaxf(m, mred[w]);
    return m;
}

__device__ __forceinline__ float bmaxcnt1(float m, float c, float* mred, float* cnt_out) {
#pragma unroll
    for (int o = 16; o; o >>= 1) {
        float m2 = __shfl_xor_sync(FULLM, m, o);
        float c2 = __shfl_xor_sync(FULLM, c, o);
        if (m2 > m) { m = m2; c = c2; }
        else if (m2 == m) { c += c2; }
    }
    int lane = threadIdx.x & 31, wid = threadIdx.x >> 5;
    if (lane == 0) { mred[wid] = m; mred[16 + wid] = c; }
    __syncthreads();
    float M = mred[0];
#pragma unroll
    for (int w = 1; w < 16; w++) M = fmaxf(M, mred[w]);
    float C = 0.0f;
#pragma unroll
    for (int w = 0; w < 16; w++) C += (mred[w] == M) ? mred[16 + w] : 0.0f;
    *cnt_out = C;
    return M;
}

// ---------------- leray: 65-tap conv, immediate taps (init only) ---------
__device__ __forceinline__ void conv_leray(float* __restrict__ dst,
                                           const float* __restrict__ src) {
    constexpr Taps TAPS = make_taps();
    int i0 = 4 * threadIdx.x;
    const float* S = src + i0 - 32;
    float4 cur = ld4(S);
    float a0 = 0.0f, a1 = 0.0f, a2 = 0.0f, a3 = 0.0f;
#pragma unroll
    for (int m = 0; m < 17; m++) {
        float4 nxt = ld4(S + 4 * m + 4);
        const float kx = TAPS.k[4 * m], ky = TAPS.k[4 * m + 1];
        const float kz = TAPS.k[4 * m + 2], kw = TAPS.k[4 * m + 3];
        a0 += kx * cur.x + ky * cur.y + kz * cur.z + kw * cur.w;
        a1 += kx * cur.y + ky * cur.z + kz * cur.w + kw * nxt.x;
        a2 += kx * cur.z + ky * cur.w + kz * nxt.x + kw * nxt.y;
        a3 += kx * cur.w + ky * nxt.x + kz * nxt.y + kw * nxt.z;
        cur = nxt;
    }
    st4h(dst, i0, make_float4(a0, a1, a2, a3));
    __syncthreads();
}

// ------- fused: up -= (lr/B)*leray^2(ub), 65-tap imm conv, no barrier ----
__device__ __forceinline__ void conv2_update(float* __restrict__ up,
                                             const float* __restrict__ ub) {
    constexpr Taps TAPS = make_taps();
    int i0 = 4 * threadIdx.x;
    const float* S = ub + i0 - 32;
    float4 cur = ld4(S);
    float a0 = 0.0f, a1 = 0.0f, a2 = 0.0f, a3 = 0.0f;
#pragma unroll
    for (int m = 0; m < 17; m++) {
        float4 nxt = ld4(S + 4 * m + 4);
        const float kx = TAPS.k2[4 * m], ky = TAPS.k2[4 * m + 1];
        const float kz = TAPS.k2[4 * m + 2], kw = TAPS.k2[4 * m + 3];
        a0 += kx * cur.x + ky * cur.y + kz * cur.z + kw * cur.w;
        a1 += kx * cur.y + ky * cur.z + kz * cur.w + kw * nxt.x;
        a2 += kx * cur.z + ky * cur.w + kz * nxt.x + kw * nxt.y;
        a3 += kx * cur.w + ky * nxt.x + kz * nxt.y + kw * nxt.z;
        cur = nxt;
    }
    float4 u = ld4(up + i0);
    st4h(up, i0, make_float4(u.x - a0, u.y - a1, u.z - a2, u.w - a3));
}

// ---- forward advect: store RAW y, one barrier, return Z -----------------
__device__ __forceinline__ float advect_fwd(float* __restrict__ dst,
                                            const float* __restrict__ r, float iZr,
                                            const float uv[5],
                                            float dt, float* red, int& sl) {
    int i0 = 4 * threadIdx.x;
    float4 r0 = ld4(r + i0);
    float rv[6] = {r[i0 - 1] * iZr, r0.x * iZr, r0.y * iZr, r0.z * iZr, r0.w * iZr,
                   r[i0 + 4] * iZr};
    float F[5];
#pragma unroll
    for (int k = 0; k < 5; k++)
        F[k] = uv[k] > 0.0f ? uv[k] * rv[k] : uv[k] * rv[k + 1];
    float y[4], part = 0.0f;
#pragma unroll
    for (int e = 0; e < 4; e++) {
        y[e] = fabsf(rv[e + 1] - dt * (F[e + 1] - F[e])) + 1e-8f;
        part += y[e];
    }
    st4h(dst, i0, make_float4(y[0], y[1], y[2], y[3]));
    return bsum1(part, red, sl);
}

// ---- forward advect for r4: also reduces dot((1-v), y_raw) --------------
__device__ __forceinline__ float advect_fwd_dot(float* __restrict__ dst,
                                                const float* __restrict__ r, float iZr,
                                                const float uv[5],
                                                const float* __restrict__ vA,
                                                float dt, float* red, float* red2,
                                                int& sl, float* dotraw_out) {
    int i0 = 4 * threadIdx.x;
    float4 r0 = ld4(r + i0);
    float rv[6] = {r[i0 - 1] * iZr, r0.x * iZr, r0.y * iZr, r0.z * iZr, r0.w * iZr,
                   r[i0 + 4] * iZr};
    float F[5];
#pragma unroll
    for (int k = 0; k < 5; k++)
        F[k] = uv[k] > 0.0f ? uv[k] * rv[k] : uv[k] * rv[k + 1];
    float4 v4 = ld4(vA + i0);
    float vb[4] = {1.0f - v4.x, 1.0f - v4.y, 1.0f - v4.z, 1.0f - v4.w};
    float y[4], part = 0.0f, part2 = 0.0f;
#pragma unroll
    for (int e = 0; e < 4; e++) {
        y[e] = fabsf(rv[e + 1] - dt * (F[e + 1] - F[e])) + 1e-8f;
        part += y[e];
        part2 += vb[e] * y[e];
    }
    st4h(dst, i0, make_float4(y[0], y[1], y[2], y[3]));
    return bsum2(part, part2, red, red2, sl, dotraw_out);
}

// ---- final outer advect (with kappa), stores NORMALIZED -----------------
__device__ __forceinline__ void advect_final(float* __restrict__ dst,
                                             const float* __restrict__ r,
                                             const float* __restrict__ u,
                                             float dt, float kap, float* red, int& sl) {
    int i0 = 4 * threadIdx.x;
    float4 r0 = ld4(r + i0);
    float rv[6] = {r[i0 - 1], r0.x, r0.y, r0.z, r0.w, r[i0 + 4]};
    float4 u0 = ld4(u + i0);
    float uv[5] = {u[i0 - 1], u0.x, u0.y, u0.z, u0.w};
    float F[5];
#pragma unroll
    for (int k = 0; k < 5; k++)
        F[k] = uv[k] > 0.0f ? uv[k] * rv[k] : uv[k] * rv[k + 1];
    float y[4], part = 0.0f;
#pragma unroll
    for (int e = 0; e < 4; e++) {
        float a = rv[e + 1] - dt * (F[e + 1] - F[e])
                + kap * dt * (rv[e + 2] + rv[e] - 2.0f * rv[e + 1]);
        y[e] = fabsf(a) + 1e-8f;
        part += y[e];
    }
    float Z = bsum1(part, red, sl);
    float iZ = 1.0f / Z;
    st4h(dst, i0, make_float4(y[0] * iZ, y[1] * iZ, y[2] * iZ, y[3] * iZ));
}

// ---- FIRST backward step (t=4): rb=(1-v), dot from fwd; SETS ub ---------
__device__ __forceinline__ float bwd_first(const float* __restrict__ rt, float iZt,
                                           float Zn, float dotraw,
                                           const float uv[5], float dt,
                                           const float* __restrict__ vA,
                                           float* __restrict__ abA,
                                           float rb[4], float ub[4],
                                           float* red, int sl) {
    int i0 = 4 * threadIdx.x;
    float iZn = 1.0f / Zn;
    float dot = dotraw * iZn;

    float4 r0 = ld4(rt + i0);
    float rr[4] = {r0.x, r0.y, r0.z, r0.w};
    float rv[6] = {rt[i0 - 1] * iZt, r0.x * iZt, r0.y * iZt, r0.z * iZt, r0.w * iZt,
                   rt[i0 + 4] * iZt};
    float F[5];
#pragma unroll
    for (int k = 0; k < 5; k++)
        F[k] = uv[k] > 0.0f ? uv[k] * rv[k] : uv[k] * rv[k + 1];

    float4 v4 = ld4(vA + i0);
    float rbl[4] = {1.0f - v4.x, 1.0f - v4.y, 1.0f - v4.z, 1.0f - v4.w};
    float ab[4], dtl = 0.0f;
#pragma unroll
    for (int e = 0; e < 4; e++) {
        float a = rv[e + 1] - dt * (F[e + 1] - F[e]);
        float s = (a > 0.0f) ? 1.0f : ((a < 0.0f) ? -1.0f : 0.0f);
        ab[e] = (rbl[e] - dot) * iZn * s;
        dtl -= ab[e] * (F[e + 1] - F[e]);
    }
    st4h(abA, i0, make_float4(ab[0], ab[1], ab[2], ab[3]));
    __syncthreads();

    float abv[6] = {abA[i0 - 1], ab[0], ab[1], ab[2], ab[3], abA[i0 + 4]};
    float Fb[5];
#pragma unroll
    for (int k = 0; k < 5; k++)
        Fb[k] = -dt * (abv[k] - abv[k + 1]);
#pragma unroll
    for (int e = 0; e < 4; e++) {
        ub[e] = Fb[e + 1] * (uv[e + 1] > 0.0f ? rv[e + 1] : rv[e + 2]);
        rb[e] = ab[e] + (uv[e + 1] > 0.0f ? Fb[e + 1] * uv[e + 1] : 0.0f)
                      + (uv[e] > 0.0f ? 0.0f : Fb[e] * uv[e]);
    }
    partial_store(rb[0] * rr[0] + rb[1] * rr[1] + rb[2] * rr[2] + rb[3] * rr[3],
                  red, sl);
    return dtl;
}

// ---- middle backward step: entry barrier publishes the pending partial --
__device__ __forceinline__ float bwd_mid(const float* __restrict__ rt, float iZt,
                                         float Zn,
                                         const float uv[5], float dt,
                                         float* __restrict__ abA,
                                         float rb[4], float ub[4],
                                         float* red, int& sl) {
    int i0 = 4 * threadIdx.x;
    __syncthreads();
    float dotraw = partial_read(red, sl);
    float iZn = 1.0f / Zn;
    float dot = dotraw * iZn;

    float4 r0 = ld4(rt + i0);
    float rr[4] = {r0.x, r0.y, r0.z, r0.w};
    float rv[6] = {rt[i0 - 1] * iZt, r0.x * iZt, r0.y * iZt, r0.z * iZt, r0.w * iZt,
                   rt[i0 + 4] * iZt};
    float F[5];
#pragma unroll
    for (int k = 0; k < 5; k++)
        F[k] = uv[k] > 0.0f ? uv[k] * rv[k] : uv[k] * rv[k + 1];

    float ab[4], dtl = 0.0f;
#pragma unroll
    for (int e = 0; e < 4; e++) {
        float a = rv[e + 1] - dt * (F[e + 1] - F[e]);
        float s = (a > 0.0f) ? 1.0f : ((a < 0.0f) ? -1.0f : 0.0f);
        ab[e] = (rb[e] - dot) * iZn * s;
        dtl -= ab[e] * (F[e + 1] - F[e]);
    }
    st4h(abA, i0, make_float4(ab[0], ab[1], ab[2], ab[3]));
    __syncthreads();

    float abv[6] = {abA[i0 - 1], ab[0], ab[1], ab[2], ab[3], abA[i0 + 4]};
    float Fb[5];
#pragma unroll
    for (int k = 0; k < 5; k++)
        Fb[k] = -dt * (abv[k] - abv[k + 1]);
#pragma unroll
    for (int e = 0; e < 4; e++) {
        ub[e] += Fb[e + 1] * (uv[e + 1] > 0.0f ? rv[e + 1] : rv[e + 2]);
        rb[e] = ab[e] + (uv[e + 1] > 0.0f ? Fb[e + 1] * uv[e + 1] : 0.0f)
                      + (uv[e] > 0.0f ? 0.0f : Fb[e] * uv[e]);
    }
    partial_store(rb[0] * rr[0] + rb[1] * rr[1] + rb[2] * rr[2] + rb[3] * rr[3],
                  red, sl);
    return dtl;
}

// ---- LAST backward step: dtbar fused into the abA-publish barrier -------
__device__ __forceinline__ float bwd_last(const float* __restrict__ rt,
                                          float Zn,
                                          const float uv[5], float dt, float dtl_in,
                                          float* __restrict__ abA,
                                          float rb[4], float ub[4],
                                          float* red, float* red2, int& sl) {
    int i0 = 4 * threadIdx.x;
    __syncthreads();
    float dotraw = partial_read(red, sl);
    float iZn = 1.0f / Zn;
    float dot = dotraw * iZn;

    float4 r0 = ld4(rt + i0);
    float rv[6] = {rt[i0 - 1], r0.x, r0.y, r0.z, r0.w, rt[i0 + 4]};  // iZt = 1
    float F[5];
#pragma unroll
    for (int k = 0; k < 5; k++)
        F[k] = uv[k] > 0.0f ? uv[k] * rv[k] : uv[k] * rv[k + 1];

    float ab[4], dtl = dtl_in;
#pragma unroll
    for (int e = 0; e < 4; e++) {
        float a = rv[e + 1] - dt * (F[e + 1] - F[e]);
        float s = (a > 0.0f) ? 1.0f : ((a < 0.0f) ? -1.0f : 0.0f);
        ab[e] = (rb[e] - dot) * iZn * s;
        dtl -= ab[e] * (F[e + 1] - F[e]);
    }
    st4h(abA, i0, make_float4(ab[0], ab[1], ab[2], ab[3]));
    float t = dtl;
#pragma unroll
    for (int o = 16; o; o >>= 1) t += __shfl_xor_sync(FULLM, t, o);
    int lane = threadIdx.x & 31, wid = threadIdx.x >> 5;
    if (lane == 0) red2[wid] = t;
    __syncthreads();
    float dtbar = 0.0f;
#pragma unroll
    for (int w = 0; w < 16; w++) dtbar += red2[w];

    float abv[6] = {abA[i0 - 1], ab[0], ab[1], ab[2], ab[3], abA[i0 + 4]};
    float Fb[5];
#pragma unroll
    for (int k = 0; k < 5; k++)
        Fb[k] = -dt * (abv[k] - abv[k + 1]);
#pragma unroll
    for (int e = 0; e < 4; e++)
        ub[e] += Fb[e + 1] * (uv[e + 1] > 0.0f ? rv[e + 1] : rv[e + 2]);
    return dtbar;
}

// ---------------- sim body: one CTA, batch b -----------------------------
#define SIM_SMEM ((2128 + 11 * LD) * 4)

__device__ void sim_body(int b, const float* __restrict__ phi_g, float* sm) {
    float* red  = sm;          // 32 (2 slots x 16)
    float* red2 = sm + 32;     // 16
    float* mred = sm + 48;     // 32
    float* phiA = sm + 80;     // 2048
    float* arr  = sm + 2128;   // 11 x LD haloed arrays
    float* vA   = arr + 0 * LD + HAL;
    float* up0A = arr + 1 * LD + HAL;
    float* upA  = arr + 2 * LD + HAL;
    float* rhoA = arr + 3 * LD + HAL;
    float* spA  = arr + 4 * LD + HAL;
    float* r1A  = arr + 5 * LD + HAL;
    float* r2A  = arr + 6 * LD + HAL;
    float* r3A  = arr + 7 * LD + HAL;
    float* r4A  = arr + 8 * LD + HAL;
    float* abA  = arr + 9 * LD + HAL;
    float* ubA  = arr + 10 * LD + HAL;

    int tid = threadIdx.x;
    int i0 = 4 * tid;
    int sl = 0;

    st4(phiA + i0, ld4(phi_g + i0));

    {
        float4 s4 = ld4(g_ssq + b * Sc + i0);
        float y0 = sqrtf(s4.x) + 1e-8f, y1 = sqrtf(s4.y) + 1e-8f;
        float y2 = sqrtf(s4.z) + 1e-8f, y3 = sqrtf(s4.w) + 1e-8f;
        float Z = bsum1(y0 + y1 + y2 + y3, red, sl);
        float iZ = 1.0f / Z;
        st4h(rhoA, i0, make_float4(y0 * iZ, y1 * iZ, y2 * iZ, y3 * iZ));
    }

    st4(r1A + i0, ld4(g_pt + b * Sc + i0));
    __syncthreads();
#pragma unroll
    for (int s = 0; s < 2; s++) {           // level 1
        int j = 2 * tid + s;
        float e = r1A[2 * j], o = r1A[2 * j + 1];
        sth(vA, 1024 + j, (e - o) * IS2);
        r2A[j] = (e + o) * IS2;
    }
    __syncthreads();
    {                                       // level 2
        float e = r2A[2 * tid], o = r2A[2 * tid + 1];
        sth(vA, 512 + tid, (e - o) * IS2);
        r1A[tid] = (e + o) * IS2;
    }
    __syncthreads();
    if (tid < 256) {                        // level 3
        float e = r1A[2 * tid], o = r1A[2 * tid + 1];
        sth(vA, 256 + tid, (e - o) * IS2);
        sth(vA, tid, (e + o) * IS2);
    }
    __syncthreads();
    {
        float4 v4 = ld4(vA + i0);
        float y0 = 45.254833995939045f * fabsf(v4.x) + 1e-8f;
        float y1 = 45.254833995939045f * fabsf(v4.y) + 1e-8f;
        float y2 = 45.254833995939045f * fabsf(v4.z) + 1e-8f;
        float y3 = 45.254833995939045f * fabsf(v4.w) + 1e-8f;
        float Z = bsum1(y0 + y1 + y2 + y3, red, sl);
        float iZ = 1.0f / Z;
        st4h(vA, i0, make_float4(y0 * iZ, y1 * iZ, y2 * iZ, y3 * iZ));
        __syncthreads();
    }

    {
        float4 v0 = ld4(vA + i0);
        float v4n = vA[i0 + 4];
        st4h(ubA, i0, make_float4(v0.y - v0.x, v0.z - v0.y, v0.w - v0.z, v4n - v0.w));
        __syncthreads();
        conv_leray(up0A, ubA);
    }

    float* rho = rhoA;
    float* spare = spA;

#pragma unroll 1
    for (int k = 0; k < 3; k++) {
        float kap = (k == 0) ? 0.01f : ((k == 1) ? 0.005f : 0.0f);

        for (int q = 4 * tid; q < LD; q += 4 * NTS)
            st4(arr + 2 * LD + q, ld4(arr + 1 * LD + q));

        {
            float4 rh = ld4(rho + i0);
            float4 ph = ld4(phiA + i0);
            float w0 = fabsf(rh.x * expf(-0.1f * (ph.x + logf(rh.x)))) + 1e-8f;
            float w1 = fabsf(rh.y * expf(-0.1f * (ph.y + logf(rh.y)))) + 1e-8f;
            float w2 = fabsf(rh.z * expf(-0.1f * (ph.z + logf(rh.z)))) + 1e-8f;
            float w3 = fabsf(rh.w * expf(-0.1f * (ph.w + logf(rh.w)))) + 1e-8f;
            float Z = bsum1(w0 + w1 + w2 + w3, red, sl);
            float iZ = 1.0f / Z;
            st4h(rho, i0, make_float4(w0 * iZ, w1 * iZ, w2 * iZ, w3 * iZ));
        }

#pragma unroll 1
        for (int is = 0; is < 5; is++) {
            float4 up4 = ld4(upA + i0);
            float a0 = fabsf(up4.x), a1 = fabsf(up4.y);
            float a2 = fabsf(up4.z), a3 = fabsf(up4.w);
            float lm = fmaxf(fmaxf(a0, a1), fmaxf(a2, a3));
            float lc = (a0 == lm ? 1.0f : 0.0f) + (a1 == lm ? 1.0f : 0.0f)
                     + (a2 == lm ? 1.0f : 0.0f) + (a3 == lm ? 1.0f : 0.0f);
            float nt;
            float m = bmaxcnt1(lm, lc, mred, &nt);
            float dt = 0.4f / (m + 1e-8f);

            float uv[5] = {upA[i0 - 1], up4.x, up4.y, up4.z, up4.w};

            float z0 = advect_fwd(r1A, rho, 1.0f, uv, dt, red, sl);
            float z1 = advect_fwd(r2A, r1A, 1.0f / z0, uv, dt, red, sl);
            float z2 = advect_fwd(r3A, r2A, 1.0f / z1, uv, dt, red, sl);
            float dotraw;
            float z3 = advect_fwd_dot(r4A, r3A, 1.0f / z2, uv, vA, dt,
                                      red, red2, sl, &dotraw);

            float rb[4], ub[4];
            float dtl = bwd_first(r3A, 1.0f / z2, z3, dotraw, uv, dt,
                                  vA, abA, rb, ub, red, sl);
            dtl += bwd_mid(r2A, 1.0f / z1, z2, uv, dt, abA, rb, ub, red, sl);
            dtl += bwd_mid(r1A, 1.0f / z0, z1, uv, dt, abA, rb, ub, red, sl);
            float dtbar = bwd_last(rho, z0, uv, dt, dtl, abA, rb, ub,
                                   red, red2, sl);

            float mbar = dtbar * (-dt * dt * 2.5f);
            {
                float inv_nt = mbar / nt;
                ub[0] += (a0 == m) ? inv_nt * ((up4.x > 0.0f) ? 1.0f : -1.0f) : 0.0f;
                ub[1] += (a1 == m) ? inv_nt * ((up4.y > 0.0f) ? 1.0f : -1.0f) : 0.0f;
                ub[2] += (a2 == m) ? inv_nt * ((up4.z > 0.0f) ? 1.0f : -1.0f) : 0.0f;
                ub[3] += (a3 == m) ? inv_nt * ((up4.w > 0.0f) ? 1.0f : -1.0f) : 0.0f;
                st4h(ubA, i0, make_float4(ub[0], ub[1], ub[2], ub[3]));
            }
            __syncthreads();

            conv2_update(upA, ubA);
        }

        {
            float4 up4 = ld4(upA + i0);
            float lm = fmaxf(fmaxf(fabsf(up4.x), fabsf(up4.y)),
                             fmaxf(fabsf(up4.z), fabsf(up4.w)));
            float mm = bmax1(lm, mred);
            float dt = 0.4f / (mm + 1e-8f);
            advect_final(spare, rho, upA, dt, kap, red, sl);
            float* tmp = rho; rho = spare; spare = tmp;
        }
    }

    {
        float4 rh = ld4(rho + i0);
        float4 v4 = ld4(vA + i0);
        float f0 = rh.x + 0.1f * v4.x, f1 = rh.y + 0.1f * v4.y;
        float f2 = rh.z + 0.1f * v4.z, f3 = rh.w + 0.1f * v4.w;
        float Z = bsum1(f0 + f1 + f2 + f3, red, sl);
        float iZ = 1.0f / Z;
        st4(g_rhof + b * Sc + i0, make_float4(f0 * iZ, f1 * iZ, f2 * iZ, f3 * iZ));
    }
}

// ---------------- sim kernel: spin on prep flags, signal done ------------
__global__ void __launch_bounds__(NTS, 1) sim_kernel(const float* __restrict__ phi) {
    extern __shared__ float sm[];
    pdl_trigger();     // out_kernel dispatches only after ALL 8 sims placed
    int b = blockIdx.x;
    if (threadIdx.x == 0) {
        while (*(volatile int*)&g_flags[b] != 256) __nanosleep(256);
        __threadfence();
    }
    __syncthreads();
    sim_body(b, phi, sm);
    __threadfence();
    __syncthreads();
    if (threadIdx.x == 0) atomicExch(&g_flags[8 + b], 1);
}

// ---------------- out: spin per-batch, then fused inverse DWT ------------
__global__ void __launch_bounds__(256) out_kernel(const float* __restrict__ bw,
                                                  float* __restrict__ out) {
    int g = blockIdx.x, b = blockIdx.y, tid = threadIdx.x;
    if (tid == 0) {
        while (*(volatile int*)&g_flags[8 + b] == 0) __nanosleep(256);
        __threadfence();
    }
    __syncthreads();

    const float* rf = g_rhof + b * Sc;
    float rfA = rf[g];
    float rf3 = rf[256 + g];
    float rf2a = rf[512 + 2 * g], rf2b = rf[512 + 2 * g + 1];
    float rf1_0 = rf[1024 + 4 * g], rf1_1 = rf[1024 + 4 * g + 1];
    float rf1_2 = rf[1024 + 4 * g + 2], rf1_3 = rf[1024 + 4 * g + 3];

    const float C8 = 0.35355339059327376220f;
    float cA = rfA * C8;
    float c3 = rf3 * C8;
    float c2arr[2] = {rf2a * 0.5f, rf2b * 0.5f};
    float c1arr[4] = {rf1_0 * IS2, rf1_1 * IS2, rf1_2 * IS2, rf1_3 * IS2};

    const float4* bw4 = (const float4*)bw;
    float4* o4 = (float4*)(out + ((size_t)b * Sc + 8 * (size_t)g) * Dc);
#pragma unroll
    for (int c = 0; c < 2; c++) {
        int c4 = tid + c * 256;
        float4 b0 = bw4[0 * 512 + c4];
        float4 b1 = bw4[1 * 512 + c4];
        float4 b2 = bw4[2 * 512 + c4];
        float4 b3 = bw4[3 * 512 + c4];
#pragma unroll
        for (int r = 0; r < 8; r++) {
            float s2 = (r < 4) ? 1.0f : -1.0f;
            float s1 = (((r >> 1) & 1) == 0) ? 1.0f : -1.0f;
            float s0 = ((r & 1) == 0) ? 1.0f : -1.0f;
            float k0 = cA;
            float k1 = s2 * c3;
            float k2 = s1 * c2arr[r >> 2];
            float k3 = s0 * c1arr[r >> 1];
            float4 o;
            o.x = k0 * b0.x + k1 * b1.x + k2 * b2.x + k3 * b3.x;
            o.y = k0 * b0.y + k1 * b1.y + k2 * b2.y + k3 * b3.y;
            o.z = k0 * b0.z + k1 * b1.z + k2 * b2.z + k3 * b3.z;
            o.w = k0 * b0.w + k1 * b1.w + k2 * b2.w + k3 * b3.w;
            o4[r * 512 + c4] = o;
        }
    }
}

// ---------------- init: zero flags each launch ---------------------------
__global__ void init_kernel() {
    if (threadIdx.x < 16) g_flags[threadIdx.x] = 0;
}

// ---------------- launch --------------------------------------------------
extern "C" void kernel_launch(void* const* d_in, const int* in_sizes, int n_in,
                              void* d_out, int out_size) {
    const float* x    = (const float*)d_in[0];
    const float* wval = (const float*)d_in[1];
    const float* phi  = (const float*)d_in[2];
    const float* bw   = (const float*)d_in[3];
    float* out = (float*)d_out;

    cudaFuncSetAttribute(sim_kernel, cudaFuncAttributeMaxDynamicSharedMemorySize,
                         SIM_SMEM);

    init_kernel<<<1, 32>>>();
    prep_kernel<<<dim3(256, 8), 256>>>(x, wval);

    // sim: PDL-dependent on prep (prep triggers at entry; sims spin on flags)
    {
        cudaLaunchConfig_t cfg = {};
        cfg.gridDim = dim3(8);
        cfg.blockDim = dim3(NTS);
        cfg.dynamicSmemBytes = SIM_SMEM;
        cfg.stream = 0;
        cudaLaunchAttribute at[1];
        at[0].id = cudaLaunchAttributeProgrammaticStreamSerialization;
        at[0].val.programmaticStreamSerializationAllowed = 1;
        cfg.attrs = at;
        cfg.numAttrs = 1;
        cudaLaunchKernelEx(&cfg, sim_kernel, phi);
    }

    // out: PDL-dependent on sim (sim triggers at entry => all 8 sims are
    // placed before any out CTA dispatches; out CTAs spin on done flags)
    {
        cudaLaunchConfig_t cfg = {};
        cfg.gridDim = dim3(256, 8);
        cfg.blockDim = dim3(256);
        cfg.dynamicSmemBytes = 0;
        cfg.stream = 0;
        cudaLaunchAttribute at[1];
        at[0].id = cudaLaunchAttributeProgrammaticStreamSerialization;
        at[0].val.programmaticStreamSerializationAllowed = 1;
        cfg.attrs = at;
        cfg.numAttrs = 1;
        cudaLaunchKernelEx(&cfg, out_kernel, bw, out);
    }
}

// round 16
// speedup vs baseline: 1.0907x; 1.0119x over previous
#include <cuda_runtime.h>
#include <math.h>

#define Sc 2048
#define Dc 2048
#define NTS 512
#define FULLM 0xffffffffu
#define IS2 0.70710678118654752440f
#define HAL 72
#define LD 2192

// ---------------- device scratch ----------------------------------------
__device__ float g_ssq[8 * Sc];   // sum over d of dwt coeff^2
__device__ float g_pt[8 * Sc];    // per-token dot with w_val
__device__ float g_rhof[8 * Sc];  // final rho_f (normalized)
__device__ int g_flags[16];       // [0..7] prep tile counts, [8..15] rhof done

__device__ __forceinline__ void pdl_trigger() {
#if defined(__CUDA_ARCH__) && __CUDA_ARCH__ >= 900
    cudaTriggerProgrammaticLaunchCompletion();
#endif
}

// ---------------- compile-time leray taps --------------------------------
struct Taps {
    float k[68];    // leray taps, disp -32..+32 (65 used, pad 68)
    float k2[68];   // 0.0125 * (kl conv kl), disp -32..+32 (65 used, pad 68)
};
__host__ __device__ constexpr Taps make_taps() {
    Taps t = {};
    double p[256] = {};
    double pn[256] = {};
    for (int it = 0; it < 50; it++) {
        for (int i = 0; i < 256; i++) {
            double l = (i > 0) ? p[i - 1] : 0.0;
            double r = (i < 255) ? p[i + 1] : 0.0;
            double bb = (i == 128) ? 1.0 : ((i == 129) ? -1.0 : 0.0);
            pn[i] = 0.5 * (r + l - bb);
        }
        for (int i = 0; i < 256; i++) p[i] = pn[i];
    }
    double kl[103] = {};
    for (int j = 0; j < 103; j++) {
        int i = 77 + j;                      // disp = j - 51
        double del = (i == 128) ? 1.0 : 0.0;
        kl[j] = del - (p[i + 1] - p[i]);
    }
    for (int j = 0; j < 68; j++)
        t.k[j] = (j < 65) ? (float)kl[j + 19] : 0.0f;
    for (int j = 0; j < 68; j++) {
        double s = 0.0;
        if (j < 65) {
            int d = j - 32;
            for (int a = -51; a <= 51; a++) {
                int e = d - a;
                if (e >= -51 && e <= 51) s += kl[a + 51] * kl[e + 51];
            }
            s *= 0.0125;                     // INNER_LR / B folded in
        }
        t.k2[j] = (float)s;
    }
    return t;
}

// ---------------- prep: DWT energies + per-token dots --------------------
__global__ void __launch_bounds__(256) prep_kernel(const float* __restrict__ x,
                                                   const float* __restrict__ wval) {
    pdl_trigger();               // sim may launch; it spins on g_flags anyway
    int g = blockIdx.x;   // 0..255
    int b = blockIdx.y;   // 0..7
    int tid = threadIdx.x;
    const float4* xv = (const float4*)(x + ((size_t)b * Sc + 8 * (size_t)g) * Dc);
    const float4* wv = (const float4*)wval;

    float acc[16];
#pragma unroll
    for (int i = 0; i < 16; i++) acc[i] = 0.0f;

#pragma unroll
    for (int c = 0; c < 2; c++) {
        int c4 = tid + c * 256;
        float4 w4 = wv[c4];
        float xr[4][8];
#pragma unroll
        for (int r = 0; r < 8; r++) {
            float4 q = xv[r * 512 + c4];
            xr[0][r] = q.x; xr[1][r] = q.y; xr[2][r] = q.z; xr[3][r] = q.w;
        }
        float wc[4] = {w4.x, w4.y, w4.z, w4.w};
#pragma unroll
        for (int cc = 0; cc < 4; cc++) {
            const float* X = xr[cc];
            float w = wc[cc];
#pragma unroll
            for (int r = 0; r < 8; r++) acc[8 + r] += X[r] * w;
            float a10 = (X[0] + X[1]) * IS2, d10 = (X[0] - X[1]) * IS2;
            float a11 = (X[2] + X[3]) * IS2, d11 = (X[2] - X[3]) * IS2;
            float a12 = (X[4] + X[5]) * IS2, d12 = (X[4] - X[5]) * IS2;
            float a13 = (X[6] + X[7]) * IS2, d13 = (X[6] - X[7]) * IS2;
            float a20 = (a10 + a11) * IS2, d20 = (a10 - a11) * IS2;
            float a21 = (a12 + a13) * IS2, d21 = (a12 - a13) * IS2;
            float a3 = (a20 + a21) * IS2, d3 = (a20 - a21) * IS2;
            acc[0] += a3 * a3;   acc[1] += d3 * d3;
            acc[2] += d20 * d20; acc[3] += d21 * d21;
            acc[4] += d10 * d10; acc[5] += d11 * d11;
            acc[6] += d12 * d12; acc[7] += d13 * d13;
        }
    }
#pragma unroll
    for (int off = 16; off; off >>= 1)
#pragma unroll
        for (int j = 0; j < 16; j++) acc[j] += __shfl_xor_sync(FULLM, acc[j], off);

    __shared__ float sred[8 * 16];
    int lane = tid & 31, wid = tid >> 5;
    if (lane == 0)
#pragma unroll
        for (int j = 0; j < 16; j++) sred[wid * 16 + j] = acc[j];
    __syncthreads();
    if (tid < 16) {
        float s = 0.0f;
#pragma unroll
        for (int w = 0; w < 8; w++) s += sred[w * 16 + tid];
        int base = b * Sc;
        if (tid < 8) {
            int idx;
            if (tid == 0) idx = g;
            else if (tid == 1) idx = 256 + g;
            else if (tid < 4) idx = 512 + 2 * g + (tid - 2);
            else idx = 1024 + 4 * g + (tid - 4);
            g_ssq[base + idx] = s;
        } else {
            g_pt[base + 8 * g + (tid - 8)] = s;
        }
    }
    __threadfence();
    __syncthreads();
    if (tid == 0) atomicAdd(&g_flags[b], 1);
}

// ---------------- small helpers ------------------------------------------
__device__ __forceinline__ float4 ld4(const float* p) { return *(const float4*)p; }
__device__ __forceinline__ void st4(float* p, float4 v) { *(float4*)p = v; }
__device__ __forceinline__ void st4h(float* A, int i0, float4 v) {
    *(float4*)(A + i0) = v;
    if (i0 < HAL) *(float4*)(A + i0 + Sc) = v;
    if (i0 >= Sc - HAL) *(float4*)(A + i0 - Sc) = v;
}
__device__ __forceinline__ void sth(float* A, int i, float v) {
    A[i] = v;
    if (i < HAL) A[i + Sc] = v;
    if (i >= Sc - HAL) A[i - Sc] = v;
}

// ------------- single-barrier reductions (512 thr, 16 warps) -------------
__device__ __forceinline__ float bsum1(float v, float* red, int& sl) {
#pragma unroll
    for (int o = 16; o; o >>= 1) v += __shfl_xor_sync(FULLM, v, o);
    int lane = threadIdx.x & 31, wid = threadIdx.x >> 5;
    if (lane == 0) red[sl * 16 + wid] = v;
    __syncthreads();
    float s = 0.0f;
    const float* rr = red + sl * 16;
#pragma unroll
    for (int w = 0; w < 16; w++) s += rr[w];
    sl ^= 1;
    return s;
}

__device__ __forceinline__ float bsum2(float v, float v2, float* red, float* red2,
                                       int& sl, float* out2) {
#pragma unroll
    for (int o = 16; o; o >>= 1) {
        v += __shfl_xor_sync(FULLM, v, o);
        v2 += __shfl_xor_sync(FULLM, v2, o);
    }
    int lane = threadIdx.x & 31, wid = threadIdx.x >> 5;
    if (lane == 0) { red[sl * 16 + wid] = v; red2[wid] = v2; }
    __syncthreads();
    float s = 0.0f, s2 = 0.0f;
    const float* rr = red + sl * 16;
#pragma unroll
    for (int w = 0; w < 16; w++) { s += rr[w]; s2 += red2[w]; }
    sl ^= 1;
    *out2 = s2;
    return s;
}

__device__ __forceinline__ void partial_store(float p, float* red, int sl) {
#pragma unroll
    for (int o = 16; o; o >>= 1) p += __shfl_xor_sync(FULLM, p, o);
    int lane = threadIdx.x & 31, wid = threadIdx.x >> 5;
    if (lane == 0) red[sl * 16 + wid] = p;
}
__device__ __forceinline__ float partial_read(const float* red, int& sl) {
    float s = 0.0f;
    const float* rr = red + sl * 16;
#pragma unroll
    for (int w = 0; w < 16; w++) s += rr[w];
    sl ^= 1;
    return s;
}

__device__ __forceinline__ float bmax1(float v, float* mred) {
#pragma unroll
    for (int o = 16; o; o >>= 1) v = fmaxf(v, __shfl_xor_sync(FULLM, v, o));
    int lane = threadIdx.x & 31, wid = threadIdx.x >> 5;
    if (lane == 0) mred[wid] = v;
    __syncthreads();
    float m = mred[0];
#pragma unroll
    for (int w = 1; w < 16; w++) m = fmaxf(m, mred[w]);
    return m;
}

__device__ __forceinline__ float bmaxcnt1(float m, float c, float* mred, float* cnt_out) {
#pragma unroll
    for (int o = 16; o; o >>= 1) {
        float m2 = __shfl_xor_sync(FULLM, m, o);
        float c2 = __shfl_xor_sync(FULLM, c, o);
        if (m2 > m) { m = m2; c = c2; }
        else if (m2 == m) { c += c2; }
    }
    int lane = threadIdx.x & 31, wid = threadIdx.x >> 5;
    if (lane == 0) { mred[wid] = m; mred[16 + wid] = c; }
    __syncthreads();
    float M = mred[0];
#pragma unroll
    for (int w = 1; w < 16; w++) M = fmaxf(M, mred[w]);
    float C = 0.0f;
#pragma unroll
    for (int w = 0; w < 16; w++) C += (mred[w] == M) ? mred[16 + w] : 0.0f;
    *cnt_out = C;
    return M;
}

// ---------------- leray: 65-tap conv, immediate taps (init only) ---------
__device__ __forceinline__ void conv_leray(float* __restrict__ dst,
                                           const float* __restrict__ src) {
    constexpr Taps TAPS = make_taps();
    int i0 = 4 * threadIdx.x;
    const float* S = src + i0 - 32;
    float4 cur = ld4(S);
    float a0 = 0.0f, a1 = 0.0f, a2 = 0.0f, a3 = 0.0f;
#pragma unroll
    for (int m = 0; m < 17; m++) {
        float4 nxt = ld4(S + 4 * m + 4);
        const float kx = TAPS.k[4 * m], ky = TAPS.k[4 * m + 1];
        const float kz = TAPS.k[4 * m + 2], kw = TAPS.k[4 * m + 3];
        a0 += kx * cur.x + ky * cur.y + kz * cur.z + kw * cur.w;
        a1 += kx * cur.y + ky * cur.z + kz * cur.w + kw * nxt.x;
        a2 += kx * cur.z + ky * cur.w + kz * nxt.x + kw * nxt.y;
        a3 += kx * cur.w + ky * nxt.x + kz * nxt.y + kw * nxt.z;
        cur = nxt;
    }
    st4h(dst, i0, make_float4(a0, a1, a2, a3));
    __syncthreads();
}

// ------- fused: up -= (lr/B)*leray^2(ub), 65-tap imm conv, no barrier ----
__device__ __forceinline__ void conv2_update(float* __restrict__ up,
                                             const float* __restrict__ ub) {
    constexpr Taps TAPS = make_taps();
    int i0 = 4 * threadIdx.x;
    const float* S = ub + i0 - 32;
    float4 cur = ld4(S);
    float a0 = 0.0f, a1 = 0.0f, a2 = 0.0f, a3 = 0.0f;
#pragma unroll
    for (int m = 0; m < 17; m++) {
        float4 nxt = ld4(S + 4 * m + 4);
        const float kx = TAPS.k2[4 * m], ky = TAPS.k2[4 * m + 1];
        const float kz = TAPS.k2[4 * m + 2], kw = TAPS.k2[4 * m + 3];
        a0 += kx * cur.x + ky * cur.y + kz * cur.z + kw * cur.w;
        a1 += kx * cur.y + ky * cur.z + kz * cur.w + kw * nxt.x;
        a2 += kx * cur.z + ky * cur.w + kz * nxt.x + kw * nxt.y;
        a3 += kx * cur.w + ky * nxt.x + kz * nxt.y + kw * nxt.z;
        cur = nxt;
    }
    float4 u = ld4(up + i0);
    st4h(up, i0, make_float4(u.x - a0, u.y - a1, u.z - a2, u.w - a3));
}

// ---- forward advect: store RAW y, one barrier, return Z -----------------
__device__ __forceinline__ float advect_fwd(float* __restrict__ dst,
                                            const float* __restrict__ r, float iZr,
                                            const float uv[5],
                                            float dt, float* red, int& sl) {
    int i0 = 4 * threadIdx.x;
    float4 r0 = ld4(r + i0);
    float rv[6] = {r[i0 - 1] * iZr, r0.x * iZr, r0.y * iZr, r0.z * iZr, r0.w * iZr,
                   r[i0 + 4] * iZr};
    float F[5];
#pragma unroll
    for (int k = 0; k < 5; k++)
        F[k] = uv[k] > 0.0f ? uv[k] * rv[k] : uv[k] * rv[k + 1];
    float y[4], part = 0.0f;
#pragma unroll
    for (int e = 0; e < 4; e++) {
        y[e] = fabsf(rv[e + 1] - dt * (F[e + 1] - F[e])) + 1e-8f;
        part += y[e];
    }
    st4h(dst, i0, make_float4(y[0], y[1], y[2], y[3]));
    return bsum1(part, red, sl);
}

// ---- forward advect for r4: also reduces dot((1-v), y_raw) --------------
__device__ __forceinline__ float advect_fwd_dot(float* __restrict__ dst,
                                                const float* __restrict__ r, float iZr,
                                                const float uv[5],
                                                const float* __restrict__ vA,
                                                float dt, float* red, float* red2,
                                                int& sl, float* dotraw_out) {
    int i0 = 4 * threadIdx.x;
    float4 r0 = ld4(r + i0);
    float rv[6] = {r[i0 - 1] * iZr, r0.x * iZr, r0.y * iZr, r0.z * iZr, r0.w * iZr,
                   r[i0 + 4] * iZr};
    float F[5];
#pragma unroll
    for (int k = 0; k < 5; k++)
        F[k] = uv[k] > 0.0f ? uv[k] * rv[k] : uv[k] * rv[k + 1];
    float4 v4 = ld4(vA + i0);
    float vb[4] = {1.0f - v4.x, 1.0f - v4.y, 1.0f - v4.z, 1.0f - v4.w};
    float y[4], part = 0.0f, part2 = 0.0f;
#pragma unroll
    for (int e = 0; e < 4; e++) {
        y[e] = fabsf(rv[e + 1] - dt * (F[e + 1] - F[e])) + 1e-8f;
        part += y[e];
        part2 += vb[e] * y[e];
    }
    st4h(dst, i0, make_float4(y[0], y[1], y[2], y[3]));
    return bsum2(part, part2, red, red2, sl, dotraw_out);
}

// ---- final outer advect (with kappa), stores NORMALIZED -----------------
__device__ __forceinline__ void advect_final(float* __restrict__ dst,
                                             const float* __restrict__ r,
                                             const float* __restrict__ u,
                                             float dt, float kap, float* red, int& sl) {
    int i0 = 4 * threadIdx.x;
    float4 r0 = ld4(r + i0);
    float rv[6] = {r[i0 - 1], r0.x, r0.y, r0.z, r0.w, r[i0 + 4]};
    float4 u0 = ld4(u + i0);
    float uv[5] = {u[i0 - 1], u0.x, u0.y, u0.z, u0.w};
    float F[5];
#pragma unroll
    for (int k = 0; k < 5; k++)
        F[k] = uv[k] > 0.0f ? uv[k] * rv[k] : uv[k] * rv[k + 1];
    float y[4], part = 0.0f;
#pragma unroll
    for (int e = 0; e < 4; e++) {
        float a = rv[e + 1] - dt * (F[e + 1] - F[e])
                + kap * dt * (rv[e + 2] + rv[e] - 2.0f * rv[e + 1]);
        y[e] = fabsf(a) + 1e-8f;
        part += y[e];
    }
    float Z = bsum1(part, red, sl);
    float iZ = 1.0f / Z;
    st4h(dst, i0, make_float4(y[0] * iZ, y[1] * iZ, y[2] * iZ, y[3] * iZ));
}

// ---- FIRST backward step (t=4): rb=(1-v), dot from fwd; SETS ub ---------
__device__ __forceinline__ float bwd_first(const float* __restrict__ rt, float iZt,
                                           float Zn, float dotraw,
                                           const float uv[5], float dt,
                                           const float* __restrict__ vA,
                                           float* __restrict__ abA,
                                           float rb[4], float ub[4],
                                           float* red, int sl) {
    int i0 = 4 * threadIdx.x;
    float iZn = 1.0f / Zn;
    float dot = dotraw * iZn;

    float4 r0 = ld4(rt + i0);
    float rr[4] = {r0.x, r0.y, r0.z, r0.w};
    float rv[6] = {rt[i0 - 1] * iZt, r0.x * iZt, r0.y * iZt, r0.z * iZt, r0.w * iZt,
                   rt[i0 + 4] * iZt};
    float F[5];
#pragma unroll
    for (int k = 0; k < 5; k++)
        F[k] = uv[k] > 0.0f ? uv[k] * rv[k] : uv[k] * rv[k + 1];

    float4 v4 = ld4(vA + i0);
    float rbl[4] = {1.0f - v4.x, 1.0f - v4.y, 1.0f - v4.z, 1.0f - v4.w};
    float ab[4], dtl = 0.0f;
#pragma unroll
    for (int e = 0; e < 4; e++) {
        float a = rv[e + 1] - dt * (F[e + 1] - F[e]);
        float s = (a > 0.0f) ? 1.0f : ((a < 0.0f) ? -1.0f : 0.0f);
        ab[e] = (rbl[e] - dot) * iZn * s;
        dtl -= ab[e] * (F[e + 1] - F[e]);
    }
    st4h(abA, i0, make_float4(ab[0], ab[1], ab[2], ab[3]));
    __syncthreads();

    float abv[6] = {abA[i0 - 1], ab[0], ab[1], ab[2], ab[3], abA[i0 + 4]};
    float Fb[5];
#pragma unroll
    for (int k = 0; k < 5; k++)
        Fb[k] = -dt * (abv[k] - abv[k + 1]);
#pragma unroll
    for (int e = 0; e < 4; e++) {
        ub[e] = Fb[e + 1] * (uv[e + 1] > 0.0f ? rv[e + 1] : rv[e + 2]);
        rb[e] = ab[e] + (uv[e + 1] > 0.0f ? Fb[e + 1] * uv[e + 1] : 0.0f)
                      + (uv[e] > 0.0f ? 0.0f : Fb[e] * uv[e]);
    }
    partial_store(rb[0] * rr[0] + rb[1] * rr[1] + rb[2] * rr[2] + rb[3] * rr[3],
                  red, sl);
    return dtl;
}

// ---- middle backward step: entry barrier publishes the pending partial --
__device__ __forceinline__ float bwd_mid(const float* __restrict__ rt, float iZt,
                                         float Zn,
                                         const float uv[5], float dt,
                                         float* __restrict__ abA,
                                         float rb[4], float ub[4],
                                         float* red, int& sl) {
    int i0 = 4 * threadIdx.x;
    __syncthreads();
    float dotraw = partial_read(red, sl);
    float iZn = 1.0f / Zn;
    float dot = dotraw * iZn;

    float4 r0 = ld4(rt + i0);
    float rr[4] = {r0.x, r0.y, r0.z, r0.w};
    float rv[6] = {rt[i0 - 1] * iZt, r0.x * iZt, r0.y * iZt, r0.z * iZt, r0.w * iZt,
                   rt[i0 + 4] * iZt};
    float F[5];
#pragma unroll
    for (int k = 0; k < 5; k++)
        F[k] = uv[k] > 0.0f ? uv[k] * rv[k] : uv[k] * rv[k + 1];

    float ab[4], dtl = 0.0f;
#pragma unroll
    for (int e = 0; e < 4; e++) {
        float a = rv[e + 1] - dt * (F[e + 1] - F[e]);
        float s = (a > 0.0f) ? 1.0f : ((a < 0.0f) ? -1.0f : 0.0f);
        ab[e] = (rb[e] - dot) * iZn * s;
        dtl -= ab[e] * (F[e + 1] - F[e]);
    }
    st4h(abA, i0, make_float4(ab[0], ab[1], ab[2], ab[3]));
    __syncthreads();

    float abv[6] = {abA[i0 - 1], ab[0], ab[1], ab[2], ab[3], abA[i0 + 4]};
    float Fb[5];
#pragma unroll
    for (int k = 0; k < 5; k++)
        Fb[k] = -dt * (abv[k] - abv[k + 1]);
#pragma unroll
    for (int e = 0; e < 4; e++) {
        ub[e] += Fb[e + 1] * (uv[e + 1] > 0.0f ? rv[e + 1] : rv[e + 2]);
        rb[e] = ab[e] + (uv[e + 1] > 0.0f ? Fb[e + 1] * uv[e + 1] : 0.0f)
                      + (uv[e] > 0.0f ? 0.0f : Fb[e] * uv[e]);
    }
    partial_store(rb[0] * rr[0] + rb[1] * rr[1] + rb[2] * rr[2] + rb[3] * rr[3],
                  red, sl);
    return dtl;
}

// ---- LAST backward step: dtbar fused into the abA-publish barrier -------
__device__ __forceinline__ float bwd_last(const float* __restrict__ rt,
                                          float Zn,
                                          const float uv[5], float dt, float dtl_in,
                                          float* __restrict__ abA,
                                          float rb[4], float ub[4],
                                          float* red, float* red2, int& sl) {
    int i0 = 4 * threadIdx.x;
    __syncthreads();
    float dotraw = partial_read(red, sl);
    float iZn = 1.0f / Zn;
    float dot = dotraw * iZn;

    float4 r0 = ld4(rt + i0);
    float rv[6] = {rt[i0 - 1], r0.x, r0.y, r0.z, r0.w, rt[i0 + 4]};  // iZt = 1
    float F[5];
#pragma unroll
    for (int k = 0; k < 5; k++)
        F[k] = uv[k] > 0.0f ? uv[k] * rv[k] : uv[k] * rv[k + 1];

    float ab[4], dtl = dtl_in;
#pragma unroll
    for (int e = 0; e < 4; e++) {
        float a = rv[e + 1] - dt * (F[e + 1] - F[e]);
        float s = (a > 0.0f) ? 1.0f : ((a < 0.0f) ? -1.0f : 0.0f);
        ab[e] = (rb[e] - dot) * iZn * s;
        dtl -= ab[e] * (F[e + 1] - F[e]);
    }
    st4h(abA, i0, make_float4(ab[0], ab[1], ab[2], ab[3]));
    float t = dtl;
#pragma unroll
    for (int o = 16; o; o >>= 1) t += __shfl_xor_sync(FULLM, t, o);
    int lane = threadIdx.x & 31, wid = threadIdx.x >> 5;
    if (lane == 0) red2[wid] = t;
    __syncthreads();
    float dtbar = 0.0f;
#pragma unroll
    for (int w = 0; w < 16; w++) dtbar += red2[w];

    float abv[6] = {abA[i0 - 1], ab[0], ab[1], ab[2], ab[3], abA[i0 + 4]};
    float Fb[5];
#pragma unroll
    for (int k = 0; k < 5; k++)
        Fb[k] = -dt * (abv[k] - abv[k + 1]);
#pragma unroll
    for (int e = 0; e < 4; e++)
        ub[e] += Fb[e + 1] * (uv[e + 1] > 0.0f ? rv[e + 1] : rv[e + 2]);
    return dtbar;
}

// ---------------- sim body: one CTA, batch b -----------------------------
#define SIM_SMEM ((2128 + 11 * LD) * 4)

__device__ void sim_body(int b, const float* __restrict__ phi_g, float* sm) {
    float* red  = sm;          // 32 (2 slots x 16)
    float* red2 = sm + 32;     // 16
    float* mred = sm + 48;     // 32
    float* phiA = sm + 80;     // 2048
    float* arr  = sm + 2128;   // 11 x LD haloed arrays
    float* vA   = arr + 0 * LD + HAL;
    float* up0A = arr + 1 * LD + HAL;
    float* upA  = arr + 2 * LD + HAL;
    float* rhoA = arr + 3 * LD + HAL;
    float* spA  = arr + 4 * LD + HAL;
    float* r1A  = arr + 5 * LD + HAL;
    float* r2A  = arr + 6 * LD + HAL;
    float* r3A  = arr + 7 * LD + HAL;
    float* r4A  = arr + 8 * LD + HAL;
    float* abA  = arr + 9 * LD + HAL;
    float* ubA  = arr + 10 * LD + HAL;

    int tid = threadIdx.x;
    int i0 = 4 * tid;
    int sl = 0;

    st4(phiA + i0, ld4(phi_g + i0));

    {
        float4 s4 = ld4(g_ssq + b * Sc + i0);
        float y0 = sqrtf(s4.x) + 1e-8f, y1 = sqrtf(s4.y) + 1e-8f;
        float y2 = sqrtf(s4.z) + 1e-8f, y3 = sqrtf(s4.w) + 1e-8f;
        float Z = bsum1(y0 + y1 + y2 + y3, red, sl);
        float iZ = 1.0f / Z;
        st4h(rhoA, i0, make_float4(y0 * iZ, y1 * iZ, y2 * iZ, y3 * iZ));
    }

    st4(r1A + i0, ld4(g_pt + b * Sc + i0));
    __syncthreads();
#pragma unroll
    for (int s = 0; s < 2; s++) {           // level 1
        int j = 2 * tid + s;
        float e = r1A[2 * j], o = r1A[2 * j + 1];
        sth(vA, 1024 + j, (e - o) * IS2);
        r2A[j] = (e + o) * IS2;
    }
    __syncthreads();
    {                                       // level 2
        float e = r2A[2 * tid], o = r2A[2 * tid + 1];
        sth(vA, 512 + tid, (e - o) * IS2);
        r1A[tid] = (e + o) * IS2;
    }
    __syncthreads();
    if (tid < 256) {                        // level 3
        float e = r1A[2 * tid], o = r1A[2 * tid + 1];
        sth(vA, 256 + tid, (e - o) * IS2);
        sth(vA, tid, (e + o) * IS2);
    }
    __syncthreads();
    {
        float4 v4 = ld4(vA + i0);
        float y0 = 45.254833995939045f * fabsf(v4.x) + 1e-8f;
        float y1 = 45.254833995939045f * fabsf(v4.y) + 1e-8f;
        float y2 = 45.254833995939045f * fabsf(v4.z) + 1e-8f;
        float y3 = 45.254833995939045f * fabsf(v4.w) + 1e-8f;
        float Z = bsum1(y0 + y1 + y2 + y3, red, sl);
        float iZ = 1.0f / Z;
        st4h(vA, i0, make_float4(y0 * iZ, y1 * iZ, y2 * iZ, y3 * iZ));
        __syncthreads();
    }

    {
        float4 v0 = ld4(vA + i0);
        float v4n = vA[i0 + 4];
        st4h(ubA, i0, make_float4(v0.y - v0.x, v0.z - v0.y, v0.w - v0.z, v4n - v0.w));
        __syncthreads();
        conv_leray(up0A, ubA);
    }

    float* rho = rhoA;
    float* spare = spA;

#pragma unroll 1
    for (int k = 0; k < 3; k++) {
        float kap = (k == 0) ? 0.01f : ((k == 1) ? 0.005f : 0.0f);

        for (int q = 4 * tid; q < LD; q += 4 * NTS)
            st4(arr + 2 * LD + q, ld4(arr + 1 * LD + q));

        {
            float4 rh = ld4(rho + i0);
            float4 ph = ld4(phiA + i0);
            float w0 = fabsf(rh.x * expf(-0.1f * (ph.x + logf(rh.x)))) + 1e-8f;
            float w1 = fabsf(rh.y * expf(-0.1f * (ph.y + logf(rh.y)))) + 1e-8f;
            float w2 = fabsf(rh.z * expf(-0.1f * (ph.z + logf(rh.z)))) + 1e-8f;
            float w3 = fabsf(rh.w * expf(-0.1f * (ph.w + logf(rh.w)))) + 1e-8f;
            float Z = bsum1(w0 + w1 + w2 + w3, red, sl);
            float iZ = 1.0f / Z;
            st4h(rho, i0, make_float4(w0 * iZ, w1 * iZ, w2 * iZ, w3 * iZ));
        }

#pragma unroll 1
        for (int is = 0; is < 5; is++) {
            float4 up4 = ld4(upA + i0);
            float a0 = fabsf(up4.x), a1 = fabsf(up4.y);
            float a2 = fabsf(up4.z), a3 = fabsf(up4.w);
            float lm = fmaxf(fmaxf(a0, a1), fmaxf(a2, a3));
            float lc = (a0 == lm ? 1.0f : 0.0f) + (a1 == lm ? 1.0f : 0.0f)
                     + (a2 == lm ? 1.0f : 0.0f) + (a3 == lm ? 1.0f : 0.0f);
            float nt;
            float m = bmaxcnt1(lm, lc, mred, &nt);
            float dt = 0.4f / (m + 1e-8f);

            float uv[5] = {upA[i0 - 1], up4.x, up4.y, up4.z, up4.w};

            float z0 = advect_fwd(r1A, rho, 1.0f, uv, dt, red, sl);
            float z1 = advect_fwd(r2A, r1A, 1.0f / z0, uv, dt, red, sl);
            float z2 = advect_fwd(r3A, r2A, 1.0f / z1, uv, dt, red, sl);
            float dotraw;
            float z3 = advect_fwd_dot(r4A, r3A, 1.0f / z2, uv, vA, dt,
                                      red, red2, sl, &dotraw);

            float rb[4], ub[4];
            float dtl = bwd_first(r3A, 1.0f / z2, z3, dotraw, uv, dt,
                                  vA, abA, rb, ub, red, sl);
            dtl += bwd_mid(r2A, 1.0f / z1, z2, uv, dt, abA, rb, ub, red, sl);
            dtl += bwd_mid(r1A, 1.0f / z0, z1, uv, dt, abA, rb, ub, red, sl);
            float dtbar = bwd_last(rho, z0, uv, dt, dtl, abA, rb, ub,
                                   red, red2, sl);

            float mbar = dtbar * (-dt * dt * 2.5f);
            {
                float inv_nt = mbar / nt;
                ub[0] += (a0 == m) ? inv_nt * ((up4.x > 0.0f) ? 1.0f : -1.0f) : 0.0f;
                ub[1] += (a1 == m) ? inv_nt * ((up4.y > 0.0f) ? 1.0f : -1.0f) : 0.0f;
                ub[2] += (a2 == m) ? inv_nt * ((up4.z > 0.0f) ? 1.0f : -1.0f) : 0.0f;
                ub[3] += (a3 == m) ? inv_nt * ((up4.w > 0.0f) ? 1.0f : -1.0f) : 0.0f;
                st4h(ubA, i0, make_float4(ub[0], ub[1], ub[2], ub[3]));
            }
            __syncthreads();

            conv2_update(upA, ubA);
        }

        {
            float4 up4 = ld4(upA + i0);
            float lm = fmaxf(fmaxf(fabsf(up4.x), fabsf(up4.y)),
                             fmaxf(fabsf(up4.z), fabsf(up4.w)));
            float mm = bmax1(lm, mred);
            float dt = 0.4f / (mm + 1e-8f);
            advect_final(spare, rho, upA, dt, kap, red, sl);
            float* tmp = rho; rho = spare; spare = tmp;
        }
    }

    {
        float4 rh = ld4(rho + i0);
        float4 v4 = ld4(vA + i0);
        float f0 = rh.x + 0.1f * v4.x, f1 = rh.y + 0.1f * v4.y;
        float f2 = rh.z + 0.1f * v4.z, f3 = rh.w + 0.1f * v4.w;
        float Z = bsum1(f0 + f1 + f2 + f3, red, sl);
        float iZ = 1.0f / Z;
        st4(g_rhof + b * Sc + i0, make_float4(f0 * iZ, f1 * iZ, f2 * iZ, f3 * iZ));
    }
}

// ---------------- sim kernel: spin on prep flags, signal done ------------
__global__ void __launch_bounds__(NTS, 1) sim_kernel(const float* __restrict__ phi) {
    extern __shared__ float sm[];
    pdl_trigger();     // out_kernel dispatches only after ALL 8 sims placed
    int b = blockIdx.x;
    if (threadIdx.x == 0) {
        while (*(volatile int*)&g_flags[b] != 256) __nanosleep(256);
        __threadfence();
    }
    __syncthreads();
    sim_body(b, phi, sm);
    __threadfence();
    __syncthreads();
    if (threadIdx.x == 0) atomicExch(&g_flags[8 + b], 1);
}

// ---------------- out: spin per-batch, then fused inverse DWT ------------
__global__ void __launch_bounds__(256) out_kernel(const float* __restrict__ bw,
                                                  float* __restrict__ out) {
    int g = blockIdx.x, b = blockIdx.y, tid = threadIdx.x;
    if (tid == 0) {
        while (*(volatile int*)&g_flags[8 + b] == 0) __nanosleep(256);
        __threadfence();
    }
    __syncthreads();

    const float* rf = g_rhof + b * Sc;
    float rfA = rf[g];
    float rf3 = rf[256 + g];
    float rf2a = rf[512 + 2 * g], rf2b = rf[512 + 2 * g + 1];
    float rf1_0 = rf[1024 + 4 * g], rf1_1 = rf[1024 + 4 * g + 1];
    float rf1_2 = rf[1024 + 4 * g + 2], rf1_3 = rf[1024 + 4 * g + 3];

    const float C8 = 0.35355339059327376220f;
    float cA = rfA * C8;
    float c3 = rf3 * C8;
    float c2arr[2] = {rf2a * 0.5f, rf2b * 0.5f};
    float c1arr[4] = {rf1_0 * IS2, rf1_1 * IS2, rf1_2 * IS2, rf1_3 * IS2};

    const float4* bw4 = (const float4*)bw;
    float4* o4 = (float4*)(out + ((size_t)b * Sc + 8 * (size_t)g) * Dc);
#pragma unroll
    for (int c = 0; c < 2; c++) {
        int c4 = tid + c * 256;
        float4 b0 = bw4[0 * 512 + c4];
        float4 b1 = bw4[1 * 512 + c4];
        float4 b2 = bw4[2 * 512 + c4];
        float4 b3 = bw4[3 * 512 + c4];
#pragma unroll
        for (int r = 0; r < 8; r++) {
            float s2 = (r < 4) ? 1.0f : -1.0f;
            float s1 = (((r >> 1) & 1) == 0) ? 1.0f : -1.0f;
            float s0 = ((r & 1) == 0) ? 1.0f : -1.0f;
            float k0 = cA;
            float k1 = s2 * c3;
            float k2 = s1 * c2arr[r >> 2];
            float k3 = s0 * c1arr[r >> 1];
            float4 o;
            o.x = k0 * b0.x + k1 * b1.x + k2 * b2.x + k3 * b3.x;
            o.y = k0 * b0.y + k1 * b1.y + k2 * b2.y + k3 * b3.y;
            o.z = k0 * b0.z + k1 * b1.z + k2 * b2.z + k3 * b3.z;
            o.w = k0 * b0.w + k1 * b1.w + k2 * b2.w + k3 * b3.w;
            o4[r * 512 + c4] = o;
        }
    }
}

// ---------------- init: zero flags each launch ---------------------------
__global__ void init_kernel() {
    if (threadIdx.x < 16) g_flags[threadIdx.x] = 0;
}

// ---------------- launch --------------------------------------------------
extern "C" void kernel_launch(void* const* d_in, const int* in_sizes, int n_in,
                              void* d_out, int out_size) {
    const float* x    = (const float*)d_in[0];
    const float* wval = (const float*)d_in[1];
    const float* phi  = (const float*)d_in[2];
    const float* bw   = (const float*)d_in[3];
    float* out = (float*)d_out;

    cudaFuncSetAttribute(sim_kernel, cudaFuncAttributeMaxDynamicSharedMemorySize,
                         SIM_SMEM);

    init_kernel<<<1, 32>>>();
    prep_kernel<<<dim3(256, 8), 256>>>(x, wval);

    // sim: PDL-dependent on prep (prep triggers at entry; sims spin on flags)
    {
        cudaLaunchConfig_t cfg = {};
        cfg.gridDim = dim3(8);
        cfg.blockDim = dim3(NTS);
        cfg.dynamicSmemBytes = SIM_SMEM;
        cfg.stream = 0;
        cudaLaunchAttribute at[1];
        at[0].id = cudaLaunchAttributeProgrammaticStreamSerialization;
        at[0].val.programmaticStreamSerializationAllowed = 1;
        cfg.attrs = at;
        cfg.numAttrs = 1;
        cudaLaunchKernelEx(&cfg, sim_kernel, phi);
    }

    // out: PDL-dependent on sim (sim triggers at entry => all 8 sims are
    // placed before any out CTA dispatches; out CTAs spin on done flags)
    {
        cudaLaunchConfig_t cfg = {};
        cfg.gridDim = dim3(256, 8);
        cfg.blockDim = dim3(256);
        cfg.dynamicSmemBytes = 0;
        cfg.stream = 0;
        cudaLaunchAttribute at[1];
        at[0].id = cudaLaunchAttributeProgrammaticStreamSerialization;
        at[0].val.programmaticStreamSerializationAllowed = 1;
        cfg.attrs = at;
        cfg.numAttrs = 1;
        cudaLaunchKernelEx(&cfg, out_kernel, bw, out);
    }
}